// round 13
// baseline (speedup 1.0000x reference)
#include <cuda_runtime.h>
#include <cuda_bf16.h>
#include <math.h>
#include <stdint.h>

#define NN 50000
#define IN_DIM 512
#define HIDD 256
#define HEADS 8
#define HC 32
#define EDGES 600000
#define KK 4
#define LN_EPS 1e-5f
#define SCAN_BLOCKS 49

// ---------------- scratch (per-topology) ----------------
__device__ float g_h1[KK * NN * HIDD];
__device__ float g_hf[NN * HIDD];
__device__ __nv_bfloat16 g_hs_hi[KK * NN * HIDD];
__device__ __nv_bfloat16 g_hs_lo[KK * NN * HIDD];
__device__ __nv_bfloat16 g_xs_hi[NN * IN_DIM];
__device__ __nv_bfloat16 g_xs_lo[NN * IN_DIM];
__device__ __nv_bfloat16 g_st_hi[NN * IN_DIM];
__device__ __nv_bfloat16 g_st_lo[NN * IN_DIM];
__device__ float g_outs[KK * NN * HIDD];
__device__ float g_dinv[KK * NN];
__device__ float g_as[KK * NN * HEADS];
__device__ float g_ad[KK * NN * HEADS];
__device__ float g_w[NN * KK];
__device__ int g_counts[KK * NN];
__device__ int g_off[KK * (NN + 1)];
__device__ int g_cursor[KK * NN];
__device__ int g_bsum[KK * SCAN_BLOCKS];
__device__ int g_csr[KK * EDGES];
__device__ __nv_bfloat16 g_bsplit[88 * 32768];

__device__ __forceinline__ float lrelu(float x) { return x > 0.f ? x : 0.2f * x; }
static inline int cdiv(int a, int b) { return (a + b - 1) / b; }

__device__ __forceinline__ uint32_t pk_bf16x2(__nv_bfloat16 a, __nv_bfloat16 b) {
    return (uint32_t)__bfloat16_as_ushort(a) | ((uint32_t)__bfloat16_as_ushort(b) << 16);
}

__device__ __forceinline__ void mma16816(float* c, const uint32_t* a, const uint32_t* b) {
    asm volatile(
        "mma.sync.aligned.m16n8k16.row.col.f32.bf16.bf16.f32 "
        "{%0,%1,%2,%3}, {%4,%5,%6,%7}, {%8,%9}, {%0,%1,%2,%3};"
        : "+f"(c[0]), "+f"(c[1]), "+f"(c[2]), "+f"(c[3])
        : "r"(a[0]), "r"(a[1]), "r"(a[2]), "r"(a[3]), "r"(b[0]), "r"(b[1]));
}

#define LDSM4(r, addr) \
    asm volatile("ldmatrix.sync.aligned.m8n8.x4.shared.b16 {%0,%1,%2,%3}, [%4];" \
                 : "=r"((r)[0]), "=r"((r)[1]), "=r"((r)[2]), "=r"((r)[3]) : "r"(addr))

__device__ __forceinline__ void cp16(uint32_t saddr, const void* gptr, bool pred) {
    int sz = pred ? 16 : 0;
    asm volatile("cp.async.cg.shared.global [%0], [%1], 16, %2;"
                 :: "r"(saddr), "l"(gptr), "r"(sz) : "memory");
}

// ---------------- weight split (all matrices, one launch) ----------------
__global__ void bsplit_all_kernel(const float* __restrict__ gW0, const float* __restrict__ gW1,
                                  const float* __restrict__ gW2, const float* __restrict__ aW,
                                  const float* __restrict__ fW1, __nv_bfloat16* __restrict__ bsw) {
    int seg = blockIdx.y;
    const float* src;
    __nv_bfloat16* dst;
    int total;
    if (seg == 16) {
        src = fW1; dst = bsw + 2621440; total = 512 * 256;
    } else {
        int topo = seg >> 2, which = seg & 3;
        __nv_bfloat16* tb = bsw + (size_t)topo * 655360;
        if (which == 0)      { src = gW0 + (size_t)topo * 512 * 256; dst = tb;          total = 512 * 256; }
        else if (which == 1) { src = gW1 + (size_t)topo * 256 * 256; dst = tb + 262144; total = 256 * 256; }
        else if (which == 2) { src = gW2 + (size_t)topo * 256 * 256; dst = tb + 393216; total = 256 * 256; }
        else                 { src = aW  + (size_t)topo * 256 * 256; dst = tb + 524288; total = 256 * 256; }
    }
    int idx = blockIdx.x * 256 + threadIdx.x;
    if (idx >= total) return;
    int kk = idx >> 8;
    int n = idx & 255;
    float w = src[idx];
    __nv_bfloat16 hi = __float2bfloat16_rn(w);
    __nv_bfloat16 lo = __float2bfloat16_rn(w - __bfloat162float(hi));
    int chunk = kk >> 5, kin = kk & 31;
    __nv_bfloat16* base = dst + (size_t)chunk * 16384;
    base[n * 32 + kin] = hi;
    base[n * 32 + kin + 8192] = lo;
}

// ---------------- activation split ----------------
__global__ void split_act_kernel(const float* __restrict__ src, __nv_bfloat16* __restrict__ dhi,
                                 __nv_bfloat16* __restrict__ dlo, int rows, int cols,
                                 int dst_ld, int dst_off) {
    int idx = blockIdx.x * 256 + threadIdx.x;
    if (idx >= rows * cols) return;
    int r = idx / cols, c = idx - r * cols;
    float v = src[idx];
    __nv_bfloat16 hi = __float2bfloat16_rn(v);
    __nv_bfloat16 lo = __float2bfloat16_rn(v - __bfloat162float(hi));
    size_t o = (size_t)r * dst_ld + dst_off + c;
    dhi[o] = hi;
    dlo[o] = lo;
}

// ---------------- CSR build (batched over topology via blockIdx.y) ----------------
__global__ void zero_int_kernel(int* p, int n) {
    int i = blockIdx.x * 256 + threadIdx.x;
    if (i < n) p[i] = 0;
}

__global__ void hist_kernel(const int* __restrict__ e0, const int* __restrict__ e1,
                            const int* __restrict__ e2, const int* __restrict__ e3,
                            int* __restrict__ counts) {
    int k = blockIdx.y;
    const int* dst = (k == 0 ? e0 : k == 1 ? e1 : k == 2 ? e2 : e3) + EDGES;
    int i = blockIdx.x * 256 + threadIdx.x;
    if (i < EDGES) atomicAdd(&counts[k * NN + dst[i]], 1);
}

__global__ void scanA_kernel(const int* __restrict__ counts, int* __restrict__ scanbuf,
                             int* __restrict__ bsum) {
    int k = blockIdx.y;
    counts += (size_t)k * NN;
    scanbuf += (size_t)k * (NN + 1);
    bsum += (size_t)k * SCAN_BLOCKS;
    __shared__ int sh[1024];
    int b = blockIdx.x, t = threadIdx.x;
    int i = b * 1024 + t;
    int v = (i < NN) ? counts[i] : 0;
    sh[t] = v;
    __syncthreads();
#pragma unroll
    for (int o = 1; o < 1024; o <<= 1) {
        int x = (t >= o) ? sh[t - o] : 0;
        __syncthreads();
        sh[t] += x;
        __syncthreads();
    }
    if (i < NN) scanbuf[i] = sh[t];
    if (t == 1023) bsum[b] = sh[t];
}

__global__ void scanC_kernel(const int* __restrict__ counts, int* __restrict__ off,
                             int* __restrict__ cursor, const int* __restrict__ bsum,
                             float* __restrict__ dinv) {
    int k = blockIdx.y;
    counts += (size_t)k * NN;
    off += (size_t)k * (NN + 1);
    cursor += (size_t)k * NN;
    bsum += (size_t)k * SCAN_BLOCKS;
    dinv += (size_t)k * NN;
    int b = blockIdx.x, t = threadIdx.x;
    int i = b * 1024 + t;
    if (i >= NN) return;
    int prefix = 0;
    for (int j = 0; j < b; j++) prefix += bsum[j];
    int cnt = counts[i];
    int excl = off[i] - cnt + prefix;
    off[i] = excl;
    cursor[i] = excl;
    dinv[i] = rsqrtf((float)cnt + 1.0f);
    if (i == NN - 1) off[NN] = excl + cnt;
}

__global__ void fillcsr_kernel(const int* __restrict__ e0, const int* __restrict__ e1,
                               const int* __restrict__ e2, const int* __restrict__ e3,
                               int* __restrict__ cursor, int* __restrict__ csr) {
    int k = blockIdx.y;
    const int* ep = (k == 0 ? e0 : k == 1 ? e1 : k == 2 ? e2 : e3);
    const int* src = ep;
    const int* dst = ep + EDGES;
    cursor += (size_t)k * NN;
    csr += (size_t)k * EDGES;
    int i = blockIdx.x * 256 + threadIdx.x;
    if (i >= EDGES) return;
    int pos = atomicAdd(&cursor[dst[i]], 1);
    csr[pos] = src[i];
}

// ---------------- tensor-core GEMM, batched over blockIdx.z ----------------
#define SA 40
#define STAGE_BYTES 40960
#define GEMM_SMEM (2 * STAGE_BYTES)

__global__ void __launch_bounds__(256, 2)
gemm_tc_kernel(const __nv_bfloat16* __restrict__ Ahi, const __nv_bfloat16* __restrict__ Alo,
               size_t strideA, int lda,
               const __nv_bfloat16* __restrict__ Bsw, size_t strideB,
               float* __restrict__ C, size_t strideC, int M, int Kd) {
    extern __shared__ char smem[];
    const uint32_t sbase = (uint32_t)__cvta_generic_to_shared(smem);

    const int z = blockIdx.z;
    Ahi += (size_t)z * strideA;
    Alo += (size_t)z * strideA;
    Bsw += (size_t)z * strideB;
    C += (size_t)z * strideC;

    const int tid = threadIdx.x;
    const int wid = tid >> 5;
    const int lane = tid & 31;
    const int g = lane >> 2;
    const int tig = lane & 3;

    const int rowBase = blockIdx.y * 128;
    const int colBase = blockIdx.x * 128;
    const int warp_m = (wid >> 2) * 64;
    const int warp_n = (wid & 3) * 32;

    const int srow = tid >> 1;
    const int shalf = tid & 1;
    const int rg = rowBase + srow;
    const bool rok = (rg < M);

    float acc[4][4][4];
#pragma unroll
    for (int i = 0; i < 4; i++)
#pragma unroll
        for (int j = 0; j < 4; j++)
#pragma unroll
            for (int q = 0; q < 4; q++) acc[i][j][q] = 0.f;

    const uint32_t soff = (srow * SA + shalf * 16) * 2;
    const uint32_t a_loff = (uint32_t)(warp_m + (lane & 15)) * (SA * 2) + ((lane & 16) ? 16 : 0);
    const uint32_t b_loff = (uint32_t)(warp_n + (lane & 7) + ((lane & 16) ? 8 : 0)) * (SA * 2)
                          + ((lane & 8) ? 16 : 0);

    auto stage_load = [&](int c, int s) {
        uint32_t st = sbase + s * STAGE_BYTES;
        size_t go = (size_t)rg * lda + (c << 5) + shalf * 16;
        cp16(st + soff,              Ahi + go,     rok);
        cp16(st + soff + 16,         Ahi + go + 8, rok);
        cp16(st + 10240 + soff,      Alo + go,     rok);
        cp16(st + 10240 + soff + 16, Alo + go + 8, rok);
        const __nv_bfloat16* Bc = Bsw + (size_t)c * 16384 + (size_t)(colBase + srow) * 32 + shalf * 16;
        cp16(st + 20480 + soff,      Bc,        true);
        cp16(st + 20480 + soff + 16, Bc + 8,    true);
        cp16(st + 30720 + soff,      Bc + 8192, true);
        cp16(st + 30720 + soff + 16, Bc + 8200, true);
    };

    const int nChunks = Kd >> 5;
    stage_load(0, 0);
    asm volatile("cp.async.commit_group;" ::: "memory");

    for (int c = 0; c < nChunks; c++) {
        __syncthreads();
        if (c + 1 < nChunks) {
            stage_load(c + 1, (c + 1) & 1);
            asm volatile("cp.async.commit_group;" ::: "memory");
            asm volatile("cp.async.wait_group 1;" ::: "memory");
        } else {
            asm volatile("cp.async.wait_group 0;" ::: "memory");
        }
        __syncthreads();

        const uint32_t st = sbase + (c & 1) * STAGE_BYTES;

#pragma unroll
        for (int ks = 0; ks < 2; ks++) {
            const uint32_t kb = ks * 32;
            uint32_t ah[4][4], al[4][4];
#pragma unroll
            for (int mt = 0; mt < 4; mt++) {
                uint32_t ad = st + a_loff + mt * (16 * SA * 2) + kb;
                LDSM4(ah[mt], ad);
                LDSM4(al[mt], ad + 10240);
            }
            uint32_t bh[4][2], bl[4][2];
#pragma unroll
            for (int p = 0; p < 2; p++) {
                uint32_t bd = st + 20480 + b_loff + p * (16 * SA * 2) + kb;
                uint32_t t4[4];
                LDSM4(t4, bd);
                bh[2 * p][0] = t4[0]; bh[2 * p][1] = t4[1];
                bh[2 * p + 1][0] = t4[2]; bh[2 * p + 1][1] = t4[3];
                LDSM4(t4, bd + 10240);
                bl[2 * p][0] = t4[0]; bl[2 * p][1] = t4[1];
                bl[2 * p + 1][0] = t4[2]; bl[2 * p + 1][1] = t4[3];
            }
#pragma unroll
            for (int mt = 0; mt < 4; mt++)
#pragma unroll
                for (int nt = 0; nt < 4; nt++) {
                    mma16816(acc[mt][nt], ah[mt], bh[nt]);
                    mma16816(acc[mt][nt], ah[mt], bl[nt]);
                    mma16816(acc[mt][nt], al[mt], bh[nt]);
                }
        }
    }

#pragma unroll
    for (int mt = 0; mt < 4; mt++) {
        int row0 = rowBase + warp_m + mt * 16 + g;
        int row1 = row0 + 8;
#pragma unroll
        for (int nt = 0; nt < 4; nt++) {
            int col = colBase + warp_n + nt * 8 + tig * 2;
            if (row0 < M)
                *(float2*)(C + (size_t)row0 * 256 + col) = make_float2(acc[mt][nt][0], acc[mt][nt][1]);
            if (row1 < M)
                *(float2*)(C + (size_t)row1 * 256 + col) = make_float2(acc[mt][nt][2], acc[mt][nt][3]);
        }
    }
}

// ---------------- GCN gather (grid.y selects topology; launched per-topo with grid.y=1) ----------------
__global__ void gcn_gather_kernel(const float* __restrict__ h, const int* __restrict__ csr,
                                  const int* __restrict__ off, const float* __restrict__ dinv,
                                  const float* __restrict__ bias,
                                  __nv_bfloat16* __restrict__ ohi, __nv_bfloat16* __restrict__ olo) {
    int tid = threadIdx.x;
    int n = blockIdx.x * 4 + (tid >> 6);
    int t = tid & 63;
    size_t base = (size_t)n * HIDD + t * 4;
    float dn = dinv[n];
    float dn2 = dn * dn;
    float4 hv = *(const float4*)(h + base);
    float4 bv = *(const float4*)(bias + t * 4);
    float4 acc = make_float4(hv.x * dn2 + bv.x, hv.y * dn2 + bv.y,
                             hv.z * dn2 + bv.z, hv.w * dn2 + bv.w);
    int beg = __ldg(&off[n]), end = __ldg(&off[n + 1]);
    for (int j = beg; j < end; j++) {
        int s = __ldg(&csr[j]);
        float cf = __ldg(&dinv[s]) * dn;
        float4 v = *(const float4*)(h + (size_t)s * HIDD + t * 4);
        acc.x += v.x * cf; acc.y += v.y * cf; acc.z += v.z * cf; acc.w += v.w * cf;
    }
    acc.x = fmaxf(acc.x, 0.f); acc.y = fmaxf(acc.y, 0.f);
    acc.z = fmaxf(acc.z, 0.f); acc.w = fmaxf(acc.w, 0.f);
    __nv_bfloat16 h0 = __float2bfloat16_rn(acc.x);
    __nv_bfloat16 h1b = __float2bfloat16_rn(acc.y);
    __nv_bfloat16 h2 = __float2bfloat16_rn(acc.z);
    __nv_bfloat16 h3 = __float2bfloat16_rn(acc.w);
    __nv_bfloat16 l0 = __float2bfloat16_rn(acc.x - __bfloat162float(h0));
    __nv_bfloat16 l1 = __float2bfloat16_rn(acc.y - __bfloat162float(h1b));
    __nv_bfloat16 l2 = __float2bfloat16_rn(acc.z - __bfloat162float(h2));
    __nv_bfloat16 l3 = __float2bfloat16_rn(acc.w - __bfloat162float(h3));
    *(uint2*)(ohi + base) = make_uint2(pk_bf16x2(h0, h1b), pk_bf16x2(h2, h3));
    *(uint2*)(olo + base) = make_uint2(pk_bf16x2(l0, l1), pk_bf16x2(l2, l3));
}

// ---------------- GAT scores (batched over blockIdx.y; streaming reads) ----------------
__global__ void gat_asad_kernel(const float* __restrict__ hg, const float* __restrict__ asrc,
                                const float* __restrict__ adst, float* __restrict__ as_,
                                float* __restrict__ ad_) {
    const int k = blockIdx.y;
    hg += (size_t)k * NN * HIDD;
    asrc += (size_t)k * HEADS * HC;
    adst += (size_t)k * HEADS * HC;
    as_ += (size_t)k * NN * HEADS;
    ad_ += (size_t)k * NN * HEADS;

    int n = blockIdx.x;
    int h = threadIdx.x >> 5, c = threadIdx.x & 31;
    float v = hg[(size_t)n * HIDD + h * HC + c];
    float s = v * asrc[h * HC + c];
    float d = v * adst[h * HC + c];
#pragma unroll
    for (int o = 16; o; o >>= 1) {
        s += __shfl_down_sync(0xffffffffu, s, o);
        d += __shfl_down_sync(0xffffffffu, d, o);
    }
    if (c == 0) {
        as_[n * HEADS + h] = s;
        ad_[n * HEADS + h] = d;
    }
}

// ---------------- GAT gather + softmax + LN (launched per-topo) ----------------
__global__ void gat_gather_ln_kernel(const float* __restrict__ hg, const int* __restrict__ csr,
                                     const int* __restrict__ off, const float* __restrict__ as_,
                                     const float* __restrict__ ad_, const float* __restrict__ ab,
                                     const float* __restrict__ lg, const float* __restrict__ lb,
                                     float* __restrict__ outp) {
    int n = blockIdx.x, c = threadIdx.x, h = c >> 5;
    int beg = __ldg(&off[n]), end = __ldg(&off[n + 1]);
    float adn = __ldg(&ad_[n * HEADS + h]);
    float eself = lrelu(__ldg(&as_[n * HEADS + h]) + adn);

    float m = eself;
    for (int j = beg; j < end; j++) {
        int s = __ldg(&csr[j]);
        m = fmaxf(m, lrelu(__ldg(&as_[s * HEADS + h]) + adn));
    }
    float denom = expf(eself - m);
    float acc = hg[(size_t)n * HIDD + c] * denom;
    for (int j = beg; j < end; j++) {
        int s = __ldg(&csr[j]);
        float w = expf(lrelu(__ldg(&as_[s * HEADS + h]) + adn) - m);
        denom += w;
        acc += hg[(size_t)s * HIDD + c] * w;
    }
    float val = acc / denom + ab[c];

    __shared__ float red[8];
    __shared__ float s_mu, s_rstd;
    float s = val;
#pragma unroll
    for (int o = 16; o; o >>= 1) s += __shfl_down_sync(0xffffffffu, s, o);
    if ((c & 31) == 0) red[c >> 5] = s;
    __syncthreads();
    if (c == 0) {
        float t = 0.f;
#pragma unroll
        for (int i = 0; i < 8; i++) t += red[i];
        s_mu = t * (1.0f / HIDD);
    }
    __syncthreads();
    float dv = val - s_mu;
    float q = dv * dv;
#pragma unroll
    for (int o = 16; o; o >>= 1) q += __shfl_down_sync(0xffffffffu, q, o);
    if ((c & 31) == 0) red[c >> 5] = q;
    __syncthreads();
    if (c == 0) {
        float t = 0.f;
#pragma unroll
        for (int i = 0; i < 8; i++) t += red[i];
        s_rstd = rsqrtf(t * (1.0f / HIDD) + LN_EPS);
    }
    __syncthreads();
    outp[(size_t)n * HIDD + c] = dv * s_rstd * lg[c] + lb[c];
}

// ---------------- fusion tail ----------------
__global__ void fuse_logits_kernel(const float* __restrict__ t, const float* __restrict__ b1,
                                   const float* __restrict__ W2, const float* __restrict__ b2,
                                   float* __restrict__ w) {
    int gw = (blockIdx.x * blockDim.x + threadIdx.x) >> 5;
    int lane = threadIdx.x & 31;
    if (gw >= NN) return;
    const float* row = t + (size_t)gw * HIDD;
    float a0 = 0.f, a1 = 0.f, a2 = 0.f, a3 = 0.f;
    for (int c = lane; c < HIDD; c += 32) {
        float tv = tanhf(row[c] + b1[c]);
        a0 += tv * W2[c * 4 + 0];
        a1 += tv * W2[c * 4 + 1];
        a2 += tv * W2[c * 4 + 2];
        a3 += tv * W2[c * 4 + 3];
    }
#pragma unroll
    for (int o = 16; o; o >>= 1) {
        a0 += __shfl_down_sync(0xffffffffu, a0, o);
        a1 += __shfl_down_sync(0xffffffffu, a1, o);
        a2 += __shfl_down_sync(0xffffffffu, a2, o);
        a3 += __shfl_down_sync(0xffffffffu, a3, o);
    }
    if (lane == 0) {
        float l0 = a0 + b2[0], l1 = a1 + b2[1], l2 = a2 + b2[2], l3 = a3 + b2[3];
        float mx = fmaxf(fmaxf(l0, l1), fmaxf(l2, l3));
        float e0 = expf(l0 - mx), e1 = expf(l1 - mx), e2 = expf(l2 - mx), e3 = expf(l3 - mx);
        float inv = 1.0f / (e0 + e1 + e2 + e3);
        w[gw * 4 + 0] = e0 * inv;
        w[gw * 4 + 1] = e1 * inv;
        w[gw * 4 + 2] = e2 * inv;
        w[gw * 4 + 3] = e3 * inv;
    }
}

__global__ void combine_kernel(const float* __restrict__ w, float* __restrict__ out) {
    int idx = blockIdx.x * 256 + threadIdx.x;
    int n = idx >> 8;
    float acc = 0.f;
#pragma unroll
    for (int k = 0; k < KK; k++) acc += w[n * KK + k] * g_outs[(size_t)k * NN * HIDD + idx];
    out[idx] = acc;
}

// ---------------- host ----------------
extern "C" void kernel_launch(void* const* d_in, const int* in_sizes, int n_in,
                              void* d_out, int out_size) {
    const float *x, *style, *stress;
    const int* ei[KK];
    int base;
    if (in_sizes[1] == 2 * EDGES) {
        x = (const float*)d_in[0];
        for (int k = 0; k < KK; k++) ei[k] = (const int*)d_in[1 + k];
        style = (const float*)d_in[5];
        stress = (const float*)d_in[6];
        base = 7;
    } else {
        x = (const float*)d_in[0];
        style = (const float*)d_in[1];
        stress = (const float*)d_in[2];
        for (int k = 0; k < KK; k++) ei[k] = (const int*)d_in[3 + k];
        base = 7;
    }
    const float* gW0 = (const float*)d_in[base + 0];
    const float* gb0 = (const float*)d_in[base + 1];
    const float* gW1 = (const float*)d_in[base + 2];
    const float* gb1 = (const float*)d_in[base + 3];
    const float* gW2 = (const float*)d_in[base + 4];
    const float* gb2 = (const float*)d_in[base + 5];
    const float* aW  = (const float*)d_in[base + 6];
    const float* aas = (const float*)d_in[base + 7];
    const float* aad = (const float*)d_in[base + 8];
    const float* ab  = (const float*)d_in[base + 9];
    const float* lg  = (const float*)d_in[base + 10];
    const float* lb  = (const float*)d_in[base + 11];
    const float* fW1 = (const float*)d_in[base + 12];
    const float* fb1 = (const float*)d_in[base + 13];
    const float* fW2 = (const float*)d_in[base + 14];
    const float* fb2 = (const float*)d_in[base + 15];

    float *h1, *hf, *outs, *dinv, *as_, *ad_, *wbuf;
    __nv_bfloat16 *hs_hi, *hs_lo, *xs_hi, *xs_lo, *st_hi, *st_lo, *bsw;
    int *counts, *off, *cursor, *bsum, *csr;
    cudaGetSymbolAddress((void**)&h1, g_h1);
    cudaGetSymbolAddress((void**)&hf, g_hf);
    cudaGetSymbolAddress((void**)&hs_hi, g_hs_hi);
    cudaGetSymbolAddress((void**)&hs_lo, g_hs_lo);
    cudaGetSymbolAddress((void**)&xs_hi, g_xs_hi);
    cudaGetSymbolAddress((void**)&xs_lo, g_xs_lo);
    cudaGetSymbolAddress((void**)&st_hi, g_st_hi);
    cudaGetSymbolAddress((void**)&st_lo, g_st_lo);
    cudaGetSymbolAddress((void**)&outs, g_outs);
    cudaGetSymbolAddress((void**)&dinv, g_dinv);
    cudaGetSymbolAddress((void**)&as_, g_as);
    cudaGetSymbolAddress((void**)&ad_, g_ad);
    cudaGetSymbolAddress((void**)&wbuf, g_w);
    cudaGetSymbolAddress((void**)&counts, g_counts);
    cudaGetSymbolAddress((void**)&off, g_off);
    cudaGetSymbolAddress((void**)&cursor, g_cursor);
    cudaGetSymbolAddress((void**)&bsum, g_bsum);
    cudaGetSymbolAddress((void**)&csr, g_csr);
    cudaGetSymbolAddress((void**)&bsw, g_bsplit);

    cudaFuncSetAttribute(gemm_tc_kernel, cudaFuncAttributeMaxDynamicSharedMemorySize, GEMM_SMEM);

    const size_t TOPO = 655360, OW1 = 262144, OW2 = 393216, OAW = 524288, OFUS = 2621440;
    const size_t NH = (size_t)NN * HIDD;
    dim3 ggridK(2, cdiv(NN, 128), KK);
    dim3 ggrid1(2, cdiv(NN, 128), 1);
    dim3 egridK(cdiv(EDGES, 256), KK);
    dim3 sgridK(SCAN_BLOCKS, KK);
    dim3 agridK(NN, KK);

    // startup
    bsplit_all_kernel<<<dim3(512, 17), 256>>>(gW0, gW1, gW2, aW, fW1, bsw);
    zero_int_kernel<<<cdiv(KK * NN, 256), 256>>>(counts, KK * NN);
    split_act_kernel<<<cdiv(NN * IN_DIM, 256), 256>>>(x, xs_hi, xs_lo, NN, IN_DIM, IN_DIM, 0);

    // GCN L0 GEMM for all topologies (A shared: strideA=0)
    gemm_tc_kernel<<<ggridK, 256, GEMM_SMEM>>>(xs_hi, xs_lo, 0, IN_DIM,
                                               bsw, TOPO, h1, NH, NN, IN_DIM);

    // CSR build (batched — small arrays)
    hist_kernel<<<egridK, 256>>>(ei[0], ei[1], ei[2], ei[3], counts);
    scanA_kernel<<<sgridK, 1024>>>(counts, off, bsum);
    scanC_kernel<<<sgridK, 1024>>>(counts, off, cursor, bsum, dinv);
    fillcsr_kernel<<<egridK, 256>>>(ei[0], ei[1], ei[2], ei[3], cursor, csr);

    // gathers per-topology (51 MB L2-resident working set each)
#define GATHER_ALL(BIAS) \
    for (int k = 0; k < KK; k++) \
        gcn_gather_kernel<<<NN / 4, 256>>>(h1 + (size_t)k * NH, csr + (size_t)k * EDGES, \
                                           off + (size_t)k * (NN + 1), dinv + (size_t)k * NN, \
                                           (BIAS) + k * HIDD, hs_hi + (size_t)k * NH, \
                                           hs_lo + (size_t)k * NH)

    GATHER_ALL(gb0);

    gemm_tc_kernel<<<ggridK, 256, GEMM_SMEM>>>(hs_hi, hs_lo, NH, HIDD,
                                               bsw + OW1, TOPO, h1, NH, NN, HIDD);
    GATHER_ALL(gb1);

    gemm_tc_kernel<<<ggridK, 256, GEMM_SMEM>>>(hs_hi, hs_lo, NH, HIDD,
                                               bsw + OW2, TOPO, h1, NH, NN, HIDD);
    GATHER_ALL(gb2);

    gemm_tc_kernel<<<ggridK, 256, GEMM_SMEM>>>(hs_hi, hs_lo, NH, HIDD,
                                               bsw + OAW, TOPO, h1, NH, NN, HIDD);
    gat_asad_kernel<<<agridK, 256>>>(h1, aas, aad, as_, ad_);
    for (int k = 0; k < KK; k++)
        gat_gather_ln_kernel<<<NN, 256>>>(h1 + (size_t)k * NH, csr + (size_t)k * EDGES,
                                          off + (size_t)k * (NN + 1),
                                          as_ + (size_t)k * NN * HEADS,
                                          ad_ + (size_t)k * NN * HEADS,
                                          ab + k * HIDD, lg + k * HIDD, lb + k * HIDD,
                                          outs + (size_t)k * NH);

    // fusion branch
    split_act_kernel<<<cdiv(NN * HIDD, 256), 256>>>(style, st_hi, st_lo, NN, HIDD, IN_DIM, 0);
    split_act_kernel<<<cdiv(NN * HIDD, 256), 256>>>(stress, st_hi, st_lo, NN, HIDD, IN_DIM, HIDD);
    gemm_tc_kernel<<<ggrid1, 256, GEMM_SMEM>>>(st_hi, st_lo, 0, IN_DIM,
                                               bsw + OFUS, 0, hf, 0, NN, 2 * HIDD);
    fuse_logits_kernel<<<cdiv(NN * 32, 256), 256>>>(hf, fb1, fW2, fb2, wbuf);
    combine_kernel<<<NN, 256>>>(wbuf, (float*)d_out);
}

// round 14
// speedup vs baseline: 1.0258x; 1.0258x over previous
#include <cuda_runtime.h>
#include <cuda_bf16.h>
#include <math.h>
#include <stdint.h>

#define NN 50000
#define IN_DIM 512
#define HIDD 256
#define HEADS 8
#define HC 32
#define EDGES 600000
#define KK 4
#define LN_EPS 1e-5f
#define SCAN_BLOCKS 49

// ---------------- scratch (per-topology) ----------------
__device__ float g_h1[KK * NN * HIDD];
__device__ float g_hf[NN * HIDD];
__device__ __nv_bfloat16 g_hs_hi[KK * NN * HIDD];
__device__ __nv_bfloat16 g_hs_lo[KK * NN * HIDD];
__device__ __nv_bfloat16 g_xs_hi[NN * IN_DIM];
__device__ __nv_bfloat16 g_xs_lo[NN * IN_DIM];
__device__ __nv_bfloat16 g_st_hi[NN * IN_DIM];
__device__ __nv_bfloat16 g_st_lo[NN * IN_DIM];
__device__ float g_outs[KK * NN * HIDD];
__device__ float g_dinv[KK * NN];
__device__ float g_as[KK * NN * HEADS];
__device__ float g_ad[KK * NN * HEADS];
__device__ float g_w[NN * KK];
__device__ int g_counts[KK * NN];
__device__ int g_off[KK * (NN + 1)];
__device__ int g_cursor[KK * NN];
__device__ int g_bsum[KK * SCAN_BLOCKS];
__device__ int g_csr[KK * EDGES];
__device__ __nv_bfloat16 g_bsplit[88 * 32768];

__device__ __forceinline__ float lrelu(float x) { return x > 0.f ? x : 0.2f * x; }
static inline int cdiv(int a, int b) { return (a + b - 1) / b; }

__device__ __forceinline__ uint32_t pk_bf16x2(__nv_bfloat16 a, __nv_bfloat16 b) {
    return (uint32_t)__bfloat16_as_ushort(a) | ((uint32_t)__bfloat16_as_ushort(b) << 16);
}

__device__ __forceinline__ void mma16816(float* c, const uint32_t* a, const uint32_t* b) {
    asm volatile(
        "mma.sync.aligned.m16n8k16.row.col.f32.bf16.bf16.f32 "
        "{%0,%1,%2,%3}, {%4,%5,%6,%7}, {%8,%9}, {%0,%1,%2,%3};"
        : "+f"(c[0]), "+f"(c[1]), "+f"(c[2]), "+f"(c[3])
        : "r"(a[0]), "r"(a[1]), "r"(a[2]), "r"(a[3]), "r"(b[0]), "r"(b[1]));
}

#define LDSM4(r, addr) \
    asm volatile("ldmatrix.sync.aligned.m8n8.x4.shared.b16 {%0,%1,%2,%3}, [%4];" \
                 : "=r"((r)[0]), "=r"((r)[1]), "=r"((r)[2]), "=r"((r)[3]) : "r"(addr))

__device__ __forceinline__ void cp16(uint32_t saddr, const void* gptr, bool pred) {
    int sz = pred ? 16 : 0;
    asm volatile("cp.async.cg.shared.global [%0], [%1], 16, %2;"
                 :: "r"(saddr), "l"(gptr), "r"(sz) : "memory");
}

// ---------------- weight split (all matrices, one launch) ----------------
__global__ void bsplit_all_kernel(const float* __restrict__ gW0, const float* __restrict__ gW1,
                                  const float* __restrict__ gW2, const float* __restrict__ aW,
                                  const float* __restrict__ fW1, __nv_bfloat16* __restrict__ bsw) {
    int seg = blockIdx.y;
    const float* src;
    __nv_bfloat16* dst;
    int total;
    if (seg == 16) {
        src = fW1; dst = bsw + 2621440; total = 512 * 256;
    } else {
        int topo = seg >> 2, which = seg & 3;
        __nv_bfloat16* tb = bsw + (size_t)topo * 655360;
        if (which == 0)      { src = gW0 + (size_t)topo * 512 * 256; dst = tb;          total = 512 * 256; }
        else if (which == 1) { src = gW1 + (size_t)topo * 256 * 256; dst = tb + 262144; total = 256 * 256; }
        else if (which == 2) { src = gW2 + (size_t)topo * 256 * 256; dst = tb + 393216; total = 256 * 256; }
        else                 { src = aW  + (size_t)topo * 256 * 256; dst = tb + 524288; total = 256 * 256; }
    }
    int idx = blockIdx.x * 256 + threadIdx.x;
    if (idx >= total) return;
    int kk = idx >> 8;
    int n = idx & 255;
    float w = src[idx];
    __nv_bfloat16 hi = __float2bfloat16_rn(w);
    __nv_bfloat16 lo = __float2bfloat16_rn(w - __bfloat162float(hi));
    int chunk = kk >> 5, kin = kk & 31;
    __nv_bfloat16* base = dst + (size_t)chunk * 16384;
    base[n * 32 + kin] = hi;
    base[n * 32 + kin + 8192] = lo;
}

// ---------------- activation split ----------------
__global__ void split_act_kernel(const float* __restrict__ src, __nv_bfloat16* __restrict__ dhi,
                                 __nv_bfloat16* __restrict__ dlo, int rows, int cols,
                                 int dst_ld, int dst_off) {
    int idx = blockIdx.x * 256 + threadIdx.x;
    if (idx >= rows * cols) return;
    int r = idx / cols, c = idx - r * cols;
    float v = src[idx];
    __nv_bfloat16 hi = __float2bfloat16_rn(v);
    __nv_bfloat16 lo = __float2bfloat16_rn(v - __bfloat162float(hi));
    size_t o = (size_t)r * dst_ld + dst_off + c;
    dhi[o] = hi;
    dlo[o] = lo;
}

// ---------------- CSR build (batched over topology via blockIdx.y) ----------------
__global__ void zero_int_kernel(int* p, int n) {
    int i = blockIdx.x * 256 + threadIdx.x;
    if (i < n) p[i] = 0;
}

__global__ void hist_kernel(const int* __restrict__ e0, const int* __restrict__ e1,
                            const int* __restrict__ e2, const int* __restrict__ e3,
                            int* __restrict__ counts) {
    int k = blockIdx.y;
    const int* dst = (k == 0 ? e0 : k == 1 ? e1 : k == 2 ? e2 : e3) + EDGES;
    int i = blockIdx.x * 256 + threadIdx.x;
    if (i < EDGES) atomicAdd(&counts[k * NN + dst[i]], 1);
}

__global__ void scanA_kernel(const int* __restrict__ counts, int* __restrict__ scanbuf,
                             int* __restrict__ bsum) {
    int k = blockIdx.y;
    counts += (size_t)k * NN;
    scanbuf += (size_t)k * (NN + 1);
    bsum += (size_t)k * SCAN_BLOCKS;
    __shared__ int sh[1024];
    int b = blockIdx.x, t = threadIdx.x;
    int i = b * 1024 + t;
    int v = (i < NN) ? counts[i] : 0;
    sh[t] = v;
    __syncthreads();
#pragma unroll
    for (int o = 1; o < 1024; o <<= 1) {
        int x = (t >= o) ? sh[t - o] : 0;
        __syncthreads();
        sh[t] += x;
        __syncthreads();
    }
    if (i < NN) scanbuf[i] = sh[t];
    if (t == 1023) bsum[b] = sh[t];
}

__global__ void scanC_kernel(const int* __restrict__ counts, int* __restrict__ off,
                             int* __restrict__ cursor, const int* __restrict__ bsum,
                             float* __restrict__ dinv) {
    int k = blockIdx.y;
    counts += (size_t)k * NN;
    off += (size_t)k * (NN + 1);
    cursor += (size_t)k * NN;
    bsum += (size_t)k * SCAN_BLOCKS;
    dinv += (size_t)k * NN;
    int b = blockIdx.x, t = threadIdx.x;
    int i = b * 1024 + t;
    if (i >= NN) return;
    int prefix = 0;
    for (int j = 0; j < b; j++) prefix += bsum[j];
    int cnt = counts[i];
    int excl = off[i] - cnt + prefix;
    off[i] = excl;
    cursor[i] = excl;
    dinv[i] = rsqrtf((float)cnt + 1.0f);
    if (i == NN - 1) off[NN] = excl + cnt;
}

__global__ void fillcsr_kernel(const int* __restrict__ e0, const int* __restrict__ e1,
                               const int* __restrict__ e2, const int* __restrict__ e3,
                               int* __restrict__ cursor, int* __restrict__ csr) {
    int k = blockIdx.y;
    const int* ep = (k == 0 ? e0 : k == 1 ? e1 : k == 2 ? e2 : e3);
    const int* src = ep;
    const int* dst = ep + EDGES;
    cursor += (size_t)k * NN;
    csr += (size_t)k * EDGES;
    int i = blockIdx.x * 256 + threadIdx.x;
    if (i >= EDGES) return;
    int pos = atomicAdd(&cursor[dst[i]], 1);
    csr[pos] = src[i];
}

// ---------------- tensor-core GEMM, batched over blockIdx.z ----------------
#define SA 40
#define STAGE_BYTES 40960
#define GEMM_SMEM (2 * STAGE_BYTES)

__global__ void __launch_bounds__(256, 2)
gemm_tc_kernel(const __nv_bfloat16* __restrict__ Ahi, const __nv_bfloat16* __restrict__ Alo,
               size_t strideA, int lda,
               const __nv_bfloat16* __restrict__ Bsw, size_t strideB,
               float* __restrict__ C, size_t strideC, int M, int Kd) {
    extern __shared__ char smem[];
    const uint32_t sbase = (uint32_t)__cvta_generic_to_shared(smem);

    const int z = blockIdx.z;
    Ahi += (size_t)z * strideA;
    Alo += (size_t)z * strideA;
    Bsw += (size_t)z * strideB;
    C += (size_t)z * strideC;

    const int tid = threadIdx.x;
    const int wid = tid >> 5;
    const int lane = tid & 31;
    const int g = lane >> 2;
    const int tig = lane & 3;

    const int rowBase = blockIdx.y * 128;
    const int colBase = blockIdx.x * 128;
    const int warp_m = (wid >> 2) * 64;
    const int warp_n = (wid & 3) * 32;

    const int srow = tid >> 1;
    const int shalf = tid & 1;
    const int rg = rowBase + srow;
    const bool rok = (rg < M);

    float acc[4][4][4];
#pragma unroll
    for (int i = 0; i < 4; i++)
#pragma unroll
        for (int j = 0; j < 4; j++)
#pragma unroll
            for (int q = 0; q < 4; q++) acc[i][j][q] = 0.f;

    const uint32_t soff = (srow * SA + shalf * 16) * 2;
    const uint32_t a_loff = (uint32_t)(warp_m + (lane & 15)) * (SA * 2) + ((lane & 16) ? 16 : 0);
    const uint32_t b_loff = (uint32_t)(warp_n + (lane & 7) + ((lane & 16) ? 8 : 0)) * (SA * 2)
                          + ((lane & 8) ? 16 : 0);

    auto stage_load = [&](int c, int s) {
        uint32_t st = sbase + s * STAGE_BYTES;
        size_t go = (size_t)rg * lda + (c << 5) + shalf * 16;
        cp16(st + soff,              Ahi + go,     rok);
        cp16(st + soff + 16,         Ahi + go + 8, rok);
        cp16(st + 10240 + soff,      Alo + go,     rok);
        cp16(st + 10240 + soff + 16, Alo + go + 8, rok);
        const __nv_bfloat16* Bc = Bsw + (size_t)c * 16384 + (size_t)(colBase + srow) * 32 + shalf * 16;
        cp16(st + 20480 + soff,      Bc,        true);
        cp16(st + 20480 + soff + 16, Bc + 8,    true);
        cp16(st + 30720 + soff,      Bc + 8192, true);
        cp16(st + 30720 + soff + 16, Bc + 8200, true);
    };

    const int nChunks = Kd >> 5;
    stage_load(0, 0);
    asm volatile("cp.async.commit_group;" ::: "memory");

    for (int c = 0; c < nChunks; c++) {
        __syncthreads();
        if (c + 1 < nChunks) {
            stage_load(c + 1, (c + 1) & 1);
            asm volatile("cp.async.commit_group;" ::: "memory");
            asm volatile("cp.async.wait_group 1;" ::: "memory");
        } else {
            asm volatile("cp.async.wait_group 0;" ::: "memory");
        }
        __syncthreads();

        const uint32_t st = sbase + (c & 1) * STAGE_BYTES;

#pragma unroll
        for (int ks = 0; ks < 2; ks++) {
            const uint32_t kb = ks * 32;
            uint32_t ah[4][4], al[4][4];
#pragma unroll
            for (int mt = 0; mt < 4; mt++) {
                uint32_t ad = st + a_loff + mt * (16 * SA * 2) + kb;
                LDSM4(ah[mt], ad);
                LDSM4(al[mt], ad + 10240);
            }
            uint32_t bh[4][2], bl[4][2];
#pragma unroll
            for (int p = 0; p < 2; p++) {
                uint32_t bd = st + 20480 + b_loff + p * (16 * SA * 2) + kb;
                uint32_t t4[4];
                LDSM4(t4, bd);
                bh[2 * p][0] = t4[0]; bh[2 * p][1] = t4[1];
                bh[2 * p + 1][0] = t4[2]; bh[2 * p + 1][1] = t4[3];
                LDSM4(t4, bd + 10240);
                bl[2 * p][0] = t4[0]; bl[2 * p][1] = t4[1];
                bl[2 * p + 1][0] = t4[2]; bl[2 * p + 1][1] = t4[3];
            }
#pragma unroll
            for (int mt = 0; mt < 4; mt++)
#pragma unroll
                for (int nt = 0; nt < 4; nt++) {
                    mma16816(acc[mt][nt], ah[mt], bh[nt]);
                    mma16816(acc[mt][nt], ah[mt], bl[nt]);
                    mma16816(acc[mt][nt], al[mt], bh[nt]);
                }
        }
    }

#pragma unroll
    for (int mt = 0; mt < 4; mt++) {
        int row0 = rowBase + warp_m + mt * 16 + g;
        int row1 = row0 + 8;
#pragma unroll
        for (int nt = 0; nt < 4; nt++) {
            int col = colBase + warp_n + nt * 8 + tig * 2;
            if (row0 < M)
                *(float2*)(C + (size_t)row0 * 256 + col) = make_float2(acc[mt][nt][0], acc[mt][nt][1]);
            if (row1 < M)
                *(float2*)(C + (size_t)row1 * 256 + col) = make_float2(acc[mt][nt][2], acc[mt][nt][3]);
        }
    }
}

// ---------------- GCN gather (batched over blockIdx.y; edge loop unrolled x4) ----------------
__global__ void gcn_gather_kernel(const float* __restrict__ h, const int* __restrict__ csr,
                                  const int* __restrict__ off, const float* __restrict__ dinv,
                                  const float* __restrict__ bias,
                                  __nv_bfloat16* __restrict__ ohi, __nv_bfloat16* __restrict__ olo) {
    const int k = blockIdx.y;
    const size_t NH = (size_t)NN * HIDD;
    h += (size_t)k * NH;
    csr += (size_t)k * EDGES;
    off += (size_t)k * (NN + 1);
    dinv += (size_t)k * NN;
    bias += (size_t)k * HIDD;
    ohi += (size_t)k * NH;
    olo += (size_t)k * NH;

    int tid = threadIdx.x;
    int n = blockIdx.x * 4 + (tid >> 6);
    int t = tid & 63;
    size_t base = (size_t)n * HIDD + t * 4;
    float dn = dinv[n];
    float dn2 = dn * dn;
    float4 hv = *(const float4*)(h + base);
    float4 bv = *(const float4*)(bias + t * 4);
    float4 acc = make_float4(hv.x * dn2 + bv.x, hv.y * dn2 + bv.y,
                             hv.z * dn2 + bv.z, hv.w * dn2 + bv.w);
    int beg = __ldg(&off[n]), end = __ldg(&off[n + 1]);
    int j = beg;
    for (; j + 4 <= end; j += 4) {
        int s0 = __ldg(&csr[j + 0]);
        int s1 = __ldg(&csr[j + 1]);
        int s2 = __ldg(&csr[j + 2]);
        int s3 = __ldg(&csr[j + 3]);
        float c0 = __ldg(&dinv[s0]) * dn;
        float c1 = __ldg(&dinv[s1]) * dn;
        float c2 = __ldg(&dinv[s2]) * dn;
        float c3 = __ldg(&dinv[s3]) * dn;
        float4 v0 = *(const float4*)(h + (size_t)s0 * HIDD + t * 4);
        float4 v1 = *(const float4*)(h + (size_t)s1 * HIDD + t * 4);
        float4 v2 = *(const float4*)(h + (size_t)s2 * HIDD + t * 4);
        float4 v3 = *(const float4*)(h + (size_t)s3 * HIDD + t * 4);
        acc.x += v0.x * c0; acc.y += v0.y * c0; acc.z += v0.z * c0; acc.w += v0.w * c0;
        acc.x += v1.x * c1; acc.y += v1.y * c1; acc.z += v1.z * c1; acc.w += v1.w * c1;
        acc.x += v2.x * c2; acc.y += v2.y * c2; acc.z += v2.z * c2; acc.w += v2.w * c2;
        acc.x += v3.x * c3; acc.y += v3.y * c3; acc.z += v3.z * c3; acc.w += v3.w * c3;
    }
    for (; j < end; j++) {
        int s = __ldg(&csr[j]);
        float cf = __ldg(&dinv[s]) * dn;
        float4 v = *(const float4*)(h + (size_t)s * HIDD + t * 4);
        acc.x += v.x * cf; acc.y += v.y * cf; acc.z += v.z * cf; acc.w += v.w * cf;
    }
    acc.x = fmaxf(acc.x, 0.f); acc.y = fmaxf(acc.y, 0.f);
    acc.z = fmaxf(acc.z, 0.f); acc.w = fmaxf(acc.w, 0.f);
    __nv_bfloat16 h0 = __float2bfloat16_rn(acc.x);
    __nv_bfloat16 h1b = __float2bfloat16_rn(acc.y);
    __nv_bfloat16 h2 = __float2bfloat16_rn(acc.z);
    __nv_bfloat16 h3 = __float2bfloat16_rn(acc.w);
    __nv_bfloat16 l0 = __float2bfloat16_rn(acc.x - __bfloat162float(h0));
    __nv_bfloat16 l1 = __float2bfloat16_rn(acc.y - __bfloat162float(h1b));
    __nv_bfloat16 l2 = __float2bfloat16_rn(acc.z - __bfloat162float(h2));
    __nv_bfloat16 l3 = __float2bfloat16_rn(acc.w - __bfloat162float(h3));
    *(uint2*)(ohi + base) = make_uint2(pk_bf16x2(h0, h1b), pk_bf16x2(h2, h3));
    *(uint2*)(olo + base) = make_uint2(pk_bf16x2(l0, l1), pk_bf16x2(l2, l3));
}

// ---------------- GAT scores (batched) ----------------
__global__ void gat_asad_kernel(const float* __restrict__ hg, const float* __restrict__ asrc,
                                const float* __restrict__ adst, float* __restrict__ as_,
                                float* __restrict__ ad_) {
    const int k = blockIdx.y;
    hg += (size_t)k * NN * HIDD;
    asrc += (size_t)k * HEADS * HC;
    adst += (size_t)k * HEADS * HC;
    as_ += (size_t)k * NN * HEADS;
    ad_ += (size_t)k * NN * HEADS;

    int n = blockIdx.x;
    int h = threadIdx.x >> 5, c = threadIdx.x & 31;
    float v = hg[(size_t)n * HIDD + h * HC + c];
    float s = v * asrc[h * HC + c];
    float d = v * adst[h * HC + c];
#pragma unroll
    for (int o = 16; o; o >>= 1) {
        s += __shfl_down_sync(0xffffffffu, s, o);
        d += __shfl_down_sync(0xffffffffu, d, o);
    }
    if (c == 0) {
        as_[n * HEADS + h] = s;
        ad_[n * HEADS + h] = d;
    }
}

// ---------------- GAT gather + softmax + LN (batched; edge loops unrolled x4) ----------------
__global__ void gat_gather_ln_kernel(const float* __restrict__ hg, const int* __restrict__ csr,
                                     const int* __restrict__ off, const float* __restrict__ as_,
                                     const float* __restrict__ ad_, const float* __restrict__ ab,
                                     const float* __restrict__ lg, const float* __restrict__ lb,
                                     float* __restrict__ outp) {
    const int k = blockIdx.y;
    const size_t NH = (size_t)NN * HIDD;
    hg += (size_t)k * NH;
    csr += (size_t)k * EDGES;
    off += (size_t)k * (NN + 1);
    as_ += (size_t)k * NN * HEADS;
    ad_ += (size_t)k * NN * HEADS;
    ab += (size_t)k * HIDD;
    lg += (size_t)k * HIDD;
    lb += (size_t)k * HIDD;
    outp += (size_t)k * NH;

    int n = blockIdx.x, c = threadIdx.x, h = c >> 5;
    int beg = __ldg(&off[n]), end = __ldg(&off[n + 1]);
    float adn = __ldg(&ad_[n * HEADS + h]);
    float eself = lrelu(__ldg(&as_[n * HEADS + h]) + adn);

    float m = eself;
    {
        int j = beg;
        for (; j + 4 <= end; j += 4) {
            int s0 = __ldg(&csr[j + 0]);
            int s1 = __ldg(&csr[j + 1]);
            int s2 = __ldg(&csr[j + 2]);
            int s3 = __ldg(&csr[j + 3]);
            float e0 = lrelu(__ldg(&as_[s0 * HEADS + h]) + adn);
            float e1 = lrelu(__ldg(&as_[s1 * HEADS + h]) + adn);
            float e2 = lrelu(__ldg(&as_[s2 * HEADS + h]) + adn);
            float e3 = lrelu(__ldg(&as_[s3 * HEADS + h]) + adn);
            m = fmaxf(m, fmaxf(fmaxf(e0, e1), fmaxf(e2, e3)));
        }
        for (; j < end; j++) {
            int s = __ldg(&csr[j]);
            m = fmaxf(m, lrelu(__ldg(&as_[s * HEADS + h]) + adn));
        }
    }

    float denom = expf(eself - m);
    float acc = hg[(size_t)n * HIDD + c] * denom;
    {
        int j = beg;
        for (; j + 4 <= end; j += 4) {
            int s0 = __ldg(&csr[j + 0]);
            int s1 = __ldg(&csr[j + 1]);
            int s2 = __ldg(&csr[j + 2]);
            int s3 = __ldg(&csr[j + 3]);
            float w0 = expf(lrelu(__ldg(&as_[s0 * HEADS + h]) + adn) - m);
            float w1 = expf(lrelu(__ldg(&as_[s1 * HEADS + h]) + adn) - m);
            float w2 = expf(lrelu(__ldg(&as_[s2 * HEADS + h]) + adn) - m);
            float w3 = expf(lrelu(__ldg(&as_[s3 * HEADS + h]) + adn) - m);
            float g0 = hg[(size_t)s0 * HIDD + c];
            float g1 = hg[(size_t)s1 * HIDD + c];
            float g2 = hg[(size_t)s2 * HIDD + c];
            float g3 = hg[(size_t)s3 * HIDD + c];
            denom += w0; acc += g0 * w0;
            denom += w1; acc += g1 * w1;
            denom += w2; acc += g2 * w2;
            denom += w3; acc += g3 * w3;
        }
        for (; j < end; j++) {
            int s = __ldg(&csr[j]);
            float w = expf(lrelu(__ldg(&as_[s * HEADS + h]) + adn) - m);
            denom += w;
            acc += hg[(size_t)s * HIDD + c] * w;
        }
    }
    float val = acc / denom + ab[c];

    __shared__ float red[8];
    __shared__ float s_mu, s_rstd;
    float s = val;
#pragma unroll
    for (int o = 16; o; o >>= 1) s += __shfl_down_sync(0xffffffffu, s, o);
    if ((c & 31) == 0) red[c >> 5] = s;
    __syncthreads();
    if (c == 0) {
        float t = 0.f;
#pragma unroll
        for (int i = 0; i < 8; i++) t += red[i];
        s_mu = t * (1.0f / HIDD);
    }
    __syncthreads();
    float dv = val - s_mu;
    float q = dv * dv;
#pragma unroll
    for (int o = 16; o; o >>= 1) q += __shfl_down_sync(0xffffffffu, q, o);
    if ((c & 31) == 0) red[c >> 5] = q;
    __syncthreads();
    if (c == 0) {
        float t = 0.f;
#pragma unroll
        for (int i = 0; i < 8; i++) t += red[i];
        s_rstd = rsqrtf(t * (1.0f / HIDD) + LN_EPS);
    }
    __syncthreads();
    outp[(size_t)n * HIDD + c] = dv * s_rstd * lg[c] + lb[c];
}

// ---------------- fusion tail ----------------
__global__ void fuse_logits_kernel(const float* __restrict__ t, const float* __restrict__ b1,
                                   const float* __restrict__ W2, const float* __restrict__ b2,
                                   float* __restrict__ w) {
    int gw = (blockIdx.x * blockDim.x + threadIdx.x) >> 5;
    int lane = threadIdx.x & 31;
    if (gw >= NN) return;
    const float* row = t + (size_t)gw * HIDD;
    float a0 = 0.f, a1 = 0.f, a2 = 0.f, a3 = 0.f;
    for (int c = lane; c < HIDD; c += 32) {
        float tv = tanhf(row[c] + b1[c]);
        a0 += tv * W2[c * 4 + 0];
        a1 += tv * W2[c * 4 + 1];
        a2 += tv * W2[c * 4 + 2];
        a3 += tv * W2[c * 4 + 3];
    }
#pragma unroll
    for (int o = 16; o; o >>= 1) {
        a0 += __shfl_down_sync(0xffffffffu, a0, o);
        a1 += __shfl_down_sync(0xffffffffu, a1, o);
        a2 += __shfl_down_sync(0xffffffffu, a2, o);
        a3 += __shfl_down_sync(0xffffffffu, a3, o);
    }
    if (lane == 0) {
        float l0 = a0 + b2[0], l1 = a1 + b2[1], l2 = a2 + b2[2], l3 = a3 + b2[3];
        float mx = fmaxf(fmaxf(l0, l1), fmaxf(l2, l3));
        float e0 = expf(l0 - mx), e1 = expf(l1 - mx), e2 = expf(l2 - mx), e3 = expf(l3 - mx);
        float inv = 1.0f / (e0 + e1 + e2 + e3);
        w[gw * 4 + 0] = e0 * inv;
        w[gw * 4 + 1] = e1 * inv;
        w[gw * 4 + 2] = e2 * inv;
        w[gw * 4 + 3] = e3 * inv;
    }
}

__global__ void combine_kernel(const float* __restrict__ w, float* __restrict__ out) {
    int idx = blockIdx.x * 256 + threadIdx.x;
    int n = idx >> 8;
    float acc = 0.f;
#pragma unroll
    for (int k = 0; k < KK; k++) acc += w[n * KK + k] * g_outs[(size_t)k * NN * HIDD + idx];
    out[idx] = acc;
}

// ---------------- host ----------------
extern "C" void kernel_launch(void* const* d_in, const int* in_sizes, int n_in,
                              void* d_out, int out_size) {
    const float *x, *style, *stress;
    const int* ei[KK];
    int base;
    if (in_sizes[1] == 2 * EDGES) {
        x = (const float*)d_in[0];
        for (int k = 0; k < KK; k++) ei[k] = (const int*)d_in[1 + k];
        style = (const float*)d_in[5];
        stress = (const float*)d_in[6];
        base = 7;
    } else {
        x = (const float*)d_in[0];
        style = (const float*)d_in[1];
        stress = (const float*)d_in[2];
        for (int k = 0; k < KK; k++) ei[k] = (const int*)d_in[3 + k];
        base = 7;
    }
    const float* gW0 = (const float*)d_in[base + 0];
    const float* gb0 = (const float*)d_in[base + 1];
    const float* gW1 = (const float*)d_in[base + 2];
    const float* gb1 = (const float*)d_in[base + 3];
    const float* gW2 = (const float*)d_in[base + 4];
    const float* gb2 = (const float*)d_in[base + 5];
    const float* aW  = (const float*)d_in[base + 6];
    const float* aas = (const float*)d_in[base + 7];
    const float* aad = (const float*)d_in[base + 8];
    const float* ab  = (const float*)d_in[base + 9];
    const float* lg  = (const float*)d_in[base + 10];
    const float* lb  = (const float*)d_in[base + 11];
    const float* fW1 = (const float*)d_in[base + 12];
    const float* fb1 = (const float*)d_in[base + 13];
    const float* fW2 = (const float*)d_in[base + 14];
    const float* fb2 = (const float*)d_in[base + 15];

    float *h1, *hf, *outs, *dinv, *as_, *ad_, *wbuf;
    __nv_bfloat16 *hs_hi, *hs_lo, *xs_hi, *xs_lo, *st_hi, *st_lo, *bsw;
    int *counts, *off, *cursor, *bsum, *csr;
    cudaGetSymbolAddress((void**)&h1, g_h1);
    cudaGetSymbolAddress((void**)&hf, g_hf);
    cudaGetSymbolAddress((void**)&hs_hi, g_hs_hi);
    cudaGetSymbolAddress((void**)&hs_lo, g_hs_lo);
    cudaGetSymbolAddress((void**)&xs_hi, g_xs_hi);
    cudaGetSymbolAddress((void**)&xs_lo, g_xs_lo);
    cudaGetSymbolAddress((void**)&st_hi, g_st_hi);
    cudaGetSymbolAddress((void**)&st_lo, g_st_lo);
    cudaGetSymbolAddress((void**)&outs, g_outs);
    cudaGetSymbolAddress((void**)&dinv, g_dinv);
    cudaGetSymbolAddress((void**)&as_, g_as);
    cudaGetSymbolAddress((void**)&ad_, g_ad);
    cudaGetSymbolAddress((void**)&wbuf, g_w);
    cudaGetSymbolAddress((void**)&counts, g_counts);
    cudaGetSymbolAddress((void**)&off, g_off);
    cudaGetSymbolAddress((void**)&cursor, g_cursor);
    cudaGetSymbolAddress((void**)&bsum, g_bsum);
    cudaGetSymbolAddress((void**)&csr, g_csr);
    cudaGetSymbolAddress((void**)&bsw, g_bsplit);

    cudaFuncSetAttribute(gemm_tc_kernel, cudaFuncAttributeMaxDynamicSharedMemorySize, GEMM_SMEM);

    const size_t TOPO = 655360, OW1 = 262144, OW2 = 393216, OAW = 524288, OFUS = 2621440;
    const size_t NH = (size_t)NN * HIDD;
    dim3 ggridK(2, cdiv(NN, 128), KK);
    dim3 ggrid1(2, cdiv(NN, 128), 1);
    dim3 egridK(cdiv(EDGES, 256), KK);
    dim3 sgridK(SCAN_BLOCKS, KK);
    dim3 ngridK(NN / 4, KK);
    dim3 agridK(NN, KK);

    // startup
    bsplit_all_kernel<<<dim3(512, 17), 256>>>(gW0, gW1, gW2, aW, fW1, bsw);
    zero_int_kernel<<<cdiv(KK * NN, 256), 256>>>(counts, KK * NN);
    split_act_kernel<<<cdiv(NN * IN_DIM, 256), 256>>>(x, xs_hi, xs_lo, NN, IN_DIM, IN_DIM, 0);

    // GCN L0 GEMM for all topologies (A shared: strideA=0)
    gemm_tc_kernel<<<ggridK, 256, GEMM_SMEM>>>(xs_hi, xs_lo, 0, IN_DIM,
                                               bsw, TOPO, h1, NH, NN, IN_DIM);

    // CSR build (all topologies)
    hist_kernel<<<egridK, 256>>>(ei[0], ei[1], ei[2], ei[3], counts);
    scanA_kernel<<<sgridK, 1024>>>(counts, off, bsum);
    scanC_kernel<<<sgridK, 1024>>>(counts, off, cursor, bsum, dinv);
    fillcsr_kernel<<<egridK, 256>>>(ei[0], ei[1], ei[2], ei[3], cursor, csr);

    gcn_gather_kernel<<<ngridK, 256>>>(h1, csr, off, dinv, gb0, hs_hi, hs_lo);

    gemm_tc_kernel<<<ggridK, 256, GEMM_SMEM>>>(hs_hi, hs_lo, NH, HIDD,
                                               bsw + OW1, TOPO, h1, NH, NN, HIDD);
    gcn_gather_kernel<<<ngridK, 256>>>(h1, csr, off, dinv, gb1, hs_hi, hs_lo);

    gemm_tc_kernel<<<ggridK, 256, GEMM_SMEM>>>(hs_hi, hs_lo, NH, HIDD,
                                               bsw + OW2, TOPO, h1, NH, NN, HIDD);
    gcn_gather_kernel<<<ngridK, 256>>>(h1, csr, off, dinv, gb2, hs_hi, hs_lo);

    gemm_tc_kernel<<<ggridK, 256, GEMM_SMEM>>>(hs_hi, hs_lo, NH, HIDD,
                                               bsw + OAW, TOPO, h1, NH, NN, HIDD);
    gat_asad_kernel<<<agridK, 256>>>(h1, aas, aad, as_, ad_);
    gat_gather_ln_kernel<<<agridK, 256>>>(h1, csr, off, as_, ad_, ab, lg, lb, outs);

    // fusion branch
    split_act_kernel<<<cdiv(NN * HIDD, 256), 256>>>(style, st_hi, st_lo, NN, HIDD, IN_DIM, 0);
    split_act_kernel<<<cdiv(NN * HIDD, 256), 256>>>(stress, st_hi, st_lo, NN, HIDD, IN_DIM, HIDD);
    gemm_tc_kernel<<<ggrid1, 256, GEMM_SMEM>>>(st_hi, st_lo, 0, IN_DIM,
                                               bsw + OFUS, 0, hf, 0, NN, 2 * HIDD);
    fuse_logits_kernel<<<cdiv(NN * 32, 256), 256>>>(hf, fb1, fW2, fb2, wbuf);
    combine_kernel<<<NN, 256>>>(wbuf, (float*)d_out);
}

// round 15
// speedup vs baseline: 1.0531x; 1.0266x over previous
#include <cuda_runtime.h>
#include <cuda_bf16.h>
#include <math.h>
#include <stdint.h>

#define NN 50000
#define IN_DIM 512
#define HIDD 256
#define HEADS 8
#define HC 32
#define EDGES 600000
#define KK 4
#define LN_EPS 1e-5f
#define SCAN_BLOCKS 49

// ---------------- scratch (per-topology) ----------------
__device__ float g_h1[KK * NN * HIDD];
__device__ float g_hf[NN * HIDD];
__device__ __nv_bfloat16 g_hs_hi[KK * NN * HIDD];
__device__ __nv_bfloat16 g_hs_lo[KK * NN * HIDD];
__device__ __nv_bfloat16 g_xs_hi[NN * IN_DIM];
__device__ __nv_bfloat16 g_xs_lo[NN * IN_DIM];
__device__ __nv_bfloat16 g_st_hi[NN * IN_DIM];
__device__ __nv_bfloat16 g_st_lo[NN * IN_DIM];
__device__ float g_outs[KK * NN * HIDD];
__device__ float g_dinv[KK * NN];
__device__ float g_as[KK * NN * HEADS];
__device__ float g_ad[KK * NN * HEADS];
__device__ float g_w[NN * KK];
__device__ int g_counts[KK * NN];
__device__ int g_off[KK * (NN + 1)];
__device__ int g_cursor[KK * NN];
__device__ int g_bsum[KK * SCAN_BLOCKS];
__device__ int g_csr[KK * EDGES];
__device__ __nv_bfloat16 g_bsplit[88 * 32768];

__device__ __forceinline__ float lrelu(float x) { return x > 0.f ? x : 0.2f * x; }
static inline int cdiv(int a, int b) { return (a + b - 1) / b; }

__device__ __forceinline__ uint32_t pk_bf16x2(__nv_bfloat16 a, __nv_bfloat16 b) {
    return (uint32_t)__bfloat16_as_ushort(a) | ((uint32_t)__bfloat16_as_ushort(b) << 16);
}

__device__ __forceinline__ void mma16816(float* c, const uint32_t* a, const uint32_t* b) {
    asm volatile(
        "mma.sync.aligned.m16n8k16.row.col.f32.bf16.bf16.f32 "
        "{%0,%1,%2,%3}, {%4,%5,%6,%7}, {%8,%9}, {%0,%1,%2,%3};"
        : "+f"(c[0]), "+f"(c[1]), "+f"(c[2]), "+f"(c[3])
        : "r"(a[0]), "r"(a[1]), "r"(a[2]), "r"(a[3]), "r"(b[0]), "r"(b[1]));
}

#define LDSM4(r, addr) \
    asm volatile("ldmatrix.sync.aligned.m8n8.x4.shared.b16 {%0,%1,%2,%3}, [%4];" \
                 : "=r"((r)[0]), "=r"((r)[1]), "=r"((r)[2]), "=r"((r)[3]) : "r"(addr))

__device__ __forceinline__ void cp16(uint32_t saddr, const void* gptr, bool pred) {
    int sz = pred ? 16 : 0;
    asm volatile("cp.async.cg.shared.global [%0], [%1], 16, %2;"
                 :: "r"(saddr), "l"(gptr), "r"(sz) : "memory");
}

// ---------------- weight split (all matrices, one launch) ----------------
__global__ void bsplit_all_kernel(const float* __restrict__ gW0, const float* __restrict__ gW1,
                                  const float* __restrict__ gW2, const float* __restrict__ aW,
                                  const float* __restrict__ fW1, __nv_bfloat16* __restrict__ bsw) {
    int seg = blockIdx.y;
    const float* src;
    __nv_bfloat16* dst;
    int total;
    if (seg == 16) {
        src = fW1; dst = bsw + 2621440; total = 512 * 256;
    } else {
        int topo = seg >> 2, which = seg & 3;
        __nv_bfloat16* tb = bsw + (size_t)topo * 655360;
        if (which == 0)      { src = gW0 + (size_t)topo * 512 * 256; dst = tb;          total = 512 * 256; }
        else if (which == 1) { src = gW1 + (size_t)topo * 256 * 256; dst = tb + 262144; total = 256 * 256; }
        else if (which == 2) { src = gW2 + (size_t)topo * 256 * 256; dst = tb + 393216; total = 256 * 256; }
        else                 { src = aW  + (size_t)topo * 256 * 256; dst = tb + 524288; total = 256 * 256; }
    }
    int idx = blockIdx.x * 256 + threadIdx.x;
    if (idx >= total) return;
    int kk = idx >> 8;
    int n = idx & 255;
    float w = src[idx];
    __nv_bfloat16 hi = __float2bfloat16_rn(w);
    __nv_bfloat16 lo = __float2bfloat16_rn(w - __bfloat162float(hi));
    int chunk = kk >> 5, kin = kk & 31;
    __nv_bfloat16* base = dst + (size_t)chunk * 16384;
    base[n * 32 + kin] = hi;
    base[n * 32 + kin + 8192] = lo;
}

// ---------------- activation split ----------------
__global__ void split_act_kernel(const float* __restrict__ src, __nv_bfloat16* __restrict__ dhi,
                                 __nv_bfloat16* __restrict__ dlo, int rows, int cols,
                                 int dst_ld, int dst_off) {
    int idx = blockIdx.x * 256 + threadIdx.x;
    if (idx >= rows * cols) return;
    int r = idx / cols, c = idx - r * cols;
    float v = src[idx];
    __nv_bfloat16 hi = __float2bfloat16_rn(v);
    __nv_bfloat16 lo = __float2bfloat16_rn(v - __bfloat162float(hi));
    size_t o = (size_t)r * dst_ld + dst_off + c;
    dhi[o] = hi;
    dlo[o] = lo;
}

// ---------------- CSR build (batched over topology via blockIdx.y) ----------------
__global__ void zero_int_kernel(int* p, int n) {
    int i = blockIdx.x * 256 + threadIdx.x;
    if (i < n) p[i] = 0;
}

__global__ void hist_kernel(const int* __restrict__ e0, const int* __restrict__ e1,
                            const int* __restrict__ e2, const int* __restrict__ e3,
                            int* __restrict__ counts) {
    int k = blockIdx.y;
    const int* dst = (k == 0 ? e0 : k == 1 ? e1 : k == 2 ? e2 : e3) + EDGES;
    int i = blockIdx.x * 256 + threadIdx.x;
    if (i < EDGES) atomicAdd(&counts[k * NN + dst[i]], 1);
}

__global__ void scanA_kernel(const int* __restrict__ counts, int* __restrict__ scanbuf,
                             int* __restrict__ bsum) {
    int k = blockIdx.y;
    counts += (size_t)k * NN;
    scanbuf += (size_t)k * (NN + 1);
    bsum += (size_t)k * SCAN_BLOCKS;
    __shared__ int sh[1024];
    int b = blockIdx.x, t = threadIdx.x;
    int i = b * 1024 + t;
    int v = (i < NN) ? counts[i] : 0;
    sh[t] = v;
    __syncthreads();
#pragma unroll
    for (int o = 1; o < 1024; o <<= 1) {
        int x = (t >= o) ? sh[t - o] : 0;
        __syncthreads();
        sh[t] += x;
        __syncthreads();
    }
    if (i < NN) scanbuf[i] = sh[t];
    if (t == 1023) bsum[b] = sh[t];
}

__global__ void scanC_kernel(const int* __restrict__ counts, int* __restrict__ off,
                             int* __restrict__ cursor, const int* __restrict__ bsum,
                             float* __restrict__ dinv) {
    int k = blockIdx.y;
    counts += (size_t)k * NN;
    off += (size_t)k * (NN + 1);
    cursor += (size_t)k * NN;
    bsum += (size_t)k * SCAN_BLOCKS;
    dinv += (size_t)k * NN;
    int b = blockIdx.x, t = threadIdx.x;
    int i = b * 1024 + t;
    if (i >= NN) return;
    int prefix = 0;
    for (int j = 0; j < b; j++) prefix += bsum[j];
    int cnt = counts[i];
    int excl = off[i] - cnt + prefix;
    off[i] = excl;
    cursor[i] = excl;
    dinv[i] = rsqrtf((float)cnt + 1.0f);
    if (i == NN - 1) off[NN] = excl + cnt;
}

__global__ void fillcsr_kernel(const int* __restrict__ e0, const int* __restrict__ e1,
                               const int* __restrict__ e2, const int* __restrict__ e3,
                               int* __restrict__ cursor, int* __restrict__ csr) {
    int k = blockIdx.y;
    const int* ep = (k == 0 ? e0 : k == 1 ? e1 : k == 2 ? e2 : e3);
    const int* src = ep;
    const int* dst = ep + EDGES;
    cursor += (size_t)k * NN;
    csr += (size_t)k * EDGES;
    int i = blockIdx.x * 256 + threadIdx.x;
    if (i >= EDGES) return;
    int pos = atomicAdd(&cursor[dst[i]], 1);
    csr[pos] = src[i];
}

// ---------------- tensor-core GEMM, batched over blockIdx.z; single barrier per chunk ----------------
// z < zAlt: A = Ahi/Alo + z*strideA, B = Bsw + z*strideB, C = C + z*strideC
// z == zAlt: A = A2hi/A2lo, B = B2, C = C2   (fusion GEMM folded in)
#define SA 40
#define STAGE_BYTES 40960
#define GEMM_SMEM (2 * STAGE_BYTES)

__global__ void __launch_bounds__(256, 2)
gemm_tc_kernel(const __nv_bfloat16* __restrict__ Ahi, const __nv_bfloat16* __restrict__ Alo,
               size_t strideA, int lda,
               const __nv_bfloat16* __restrict__ Bsw, size_t strideB,
               float* __restrict__ C, size_t strideC, int M, int Kd, int zAlt,
               const __nv_bfloat16* __restrict__ A2hi, const __nv_bfloat16* __restrict__ A2lo,
               const __nv_bfloat16* __restrict__ B2, float* __restrict__ C2) {
    extern __shared__ char smem[];
    const uint32_t sbase = (uint32_t)__cvta_generic_to_shared(smem);

    const int z = blockIdx.z;
    if (z == zAlt) {
        Ahi = A2hi; Alo = A2lo; Bsw = B2; C = C2;
    } else {
        Ahi += (size_t)z * strideA;
        Alo += (size_t)z * strideA;
        Bsw += (size_t)z * strideB;
        C += (size_t)z * strideC;
    }

    const int tid = threadIdx.x;
    const int wid = tid >> 5;
    const int lane = tid & 31;
    const int g = lane >> 2;
    const int tig = lane & 3;

    const int rowBase = blockIdx.y * 128;
    const int colBase = blockIdx.x * 128;
    const int warp_m = (wid >> 2) * 64;
    const int warp_n = (wid & 3) * 32;

    const int srow = tid >> 1;
    const int shalf = tid & 1;
    const int rg = rowBase + srow;
    const bool rok = (rg < M);

    float acc[4][4][4];
#pragma unroll
    for (int i = 0; i < 4; i++)
#pragma unroll
        for (int j = 0; j < 4; j++)
#pragma unroll
            for (int q = 0; q < 4; q++) acc[i][j][q] = 0.f;

    const uint32_t soff = (srow * SA + shalf * 16) * 2;
    const uint32_t a_loff = (uint32_t)(warp_m + (lane & 15)) * (SA * 2) + ((lane & 16) ? 16 : 0);
    const uint32_t b_loff = (uint32_t)(warp_n + (lane & 7) + ((lane & 16) ? 8 : 0)) * (SA * 2)
                          + ((lane & 8) ? 16 : 0);

    auto stage_load = [&](int c, int s) {
        uint32_t st = sbase + s * STAGE_BYTES;
        size_t go = (size_t)rg * lda + (c << 5) + shalf * 16;
        cp16(st + soff,              Ahi + go,     rok);
        cp16(st + soff + 16,         Ahi + go + 8, rok);
        cp16(st + 10240 + soff,      Alo + go,     rok);
        cp16(st + 10240 + soff + 16, Alo + go + 8, rok);
        const __nv_bfloat16* Bc = Bsw + (size_t)c * 16384 + (size_t)(colBase + srow) * 32 + shalf * 16;
        cp16(st + 20480 + soff,      Bc,        true);
        cp16(st + 20480 + soff + 16, Bc + 8,    true);
        cp16(st + 30720 + soff,      Bc + 8192, true);
        cp16(st + 30720 + soff + 16, Bc + 8200, true);
    };

    const int nChunks = Kd >> 5;
    stage_load(0, 0);
    asm volatile("cp.async.commit_group;" ::: "memory");

    for (int c = 0; c < nChunks; c++) {
        asm volatile("cp.async.wait_group 0;" ::: "memory");  // own stage-c copies landed
        __syncthreads();  // all landed & prior compute done -> other buffer free
        if (c + 1 < nChunks) {
            stage_load(c + 1, (c + 1) & 1);
            asm volatile("cp.async.commit_group;" ::: "memory");
        }

        const uint32_t st = sbase + (c & 1) * STAGE_BYTES;

#pragma unroll
        for (int ks = 0; ks < 2; ks++) {
            const uint32_t kb = ks * 32;
            uint32_t ah[4][4], al[4][4];
#pragma unroll
            for (int mt = 0; mt < 4; mt++) {
                uint32_t ad = st + a_loff + mt * (16 * SA * 2) + kb;
                LDSM4(ah[mt], ad);
                LDSM4(al[mt], ad + 10240);
            }
            uint32_t bh[4][2], bl[4][2];
#pragma unroll
            for (int p = 0; p < 2; p++) {
                uint32_t bd = st + 20480 + b_loff + p * (16 * SA * 2) + kb;
                uint32_t t4[4];
                LDSM4(t4, bd);
                bh[2 * p][0] = t4[0]; bh[2 * p][1] = t4[1];
                bh[2 * p + 1][0] = t4[2]; bh[2 * p + 1][1] = t4[3];
                LDSM4(t4, bd + 10240);
                bl[2 * p][0] = t4[0]; bl[2 * p][1] = t4[1];
                bl[2 * p + 1][0] = t4[2]; bl[2 * p + 1][1] = t4[3];
            }
#pragma unroll
            for (int mt = 0; mt < 4; mt++)
#pragma unroll
                for (int nt = 0; nt < 4; nt++) {
                    mma16816(acc[mt][nt], ah[mt], bh[nt]);
                    mma16816(acc[mt][nt], ah[mt], bl[nt]);
                    mma16816(acc[mt][nt], al[mt], bh[nt]);
                }
        }
    }

#pragma unroll
    for (int mt = 0; mt < 4; mt++) {
        int row0 = rowBase + warp_m + mt * 16 + g;
        int row1 = row0 + 8;
#pragma unroll
        for (int nt = 0; nt < 4; nt++) {
            int col = colBase + warp_n + nt * 8 + tig * 2;
            if (row0 < M)
                *(float2*)(C + (size_t)row0 * 256 + col) = make_float2(acc[mt][nt][0], acc[mt][nt][1]);
            if (row1 < M)
                *(float2*)(C + (size_t)row1 * 256 + col) = make_float2(acc[mt][nt][2], acc[mt][nt][3]);
        }
    }
}

// ---------------- GCN gather (batched over blockIdx.y; edge loop unrolled x4) ----------------
__global__ void gcn_gather_kernel(const float* __restrict__ h, const int* __restrict__ csr,
                                  const int* __restrict__ off, const float* __restrict__ dinv,
                                  const float* __restrict__ bias,
                                  __nv_bfloat16* __restrict__ ohi, __nv_bfloat16* __restrict__ olo) {
    const int k = blockIdx.y;
    const size_t NH = (size_t)NN * HIDD;
    h += (size_t)k * NH;
    csr += (size_t)k * EDGES;
    off += (size_t)k * (NN + 1);
    dinv += (size_t)k * NN;
    bias += (size_t)k * HIDD;
    ohi += (size_t)k * NH;
    olo += (size_t)k * NH;

    int tid = threadIdx.x;
    int n = blockIdx.x * 4 + (tid >> 6);
    int t = tid & 63;
    size_t base = (size_t)n * HIDD + t * 4;
    float dn = dinv[n];
    float dn2 = dn * dn;
    float4 hv = *(const float4*)(h + base);
    float4 bv = *(const float4*)(bias + t * 4);
    float4 acc = make_float4(hv.x * dn2 + bv.x, hv.y * dn2 + bv.y,
                             hv.z * dn2 + bv.z, hv.w * dn2 + bv.w);
    int beg = __ldg(&off[n]), end = __ldg(&off[n + 1]);
    int j = beg;
    for (; j + 4 <= end; j += 4) {
        int s0 = __ldg(&csr[j + 0]);
        int s1 = __ldg(&csr[j + 1]);
        int s2 = __ldg(&csr[j + 2]);
        int s3 = __ldg(&csr[j + 3]);
        float c0 = __ldg(&dinv[s0]) * dn;
        float c1 = __ldg(&dinv[s1]) * dn;
        float c2 = __ldg(&dinv[s2]) * dn;
        float c3 = __ldg(&dinv[s3]) * dn;
        float4 v0 = *(const float4*)(h + (size_t)s0 * HIDD + t * 4);
        float4 v1 = *(const float4*)(h + (size_t)s1 * HIDD + t * 4);
        float4 v2 = *(const float4*)(h + (size_t)s2 * HIDD + t * 4);
        float4 v3 = *(const float4*)(h + (size_t)s3 * HIDD + t * 4);
        acc.x += v0.x * c0; acc.y += v0.y * c0; acc.z += v0.z * c0; acc.w += v0.w * c0;
        acc.x += v1.x * c1; acc.y += v1.y * c1; acc.z += v1.z * c1; acc.w += v1.w * c1;
        acc.x += v2.x * c2; acc.y += v2.y * c2; acc.z += v2.z * c2; acc.w += v2.w * c2;
        acc.x += v3.x * c3; acc.y += v3.y * c3; acc.z += v3.z * c3; acc.w += v3.w * c3;
    }
    for (; j < end; j++) {
        int s = __ldg(&csr[j]);
        float cf = __ldg(&dinv[s]) * dn;
        float4 v = *(const float4*)(h + (size_t)s * HIDD + t * 4);
        acc.x += v.x * cf; acc.y += v.y * cf; acc.z += v.z * cf; acc.w += v.w * cf;
    }
    acc.x = fmaxf(acc.x, 0.f); acc.y = fmaxf(acc.y, 0.f);
    acc.z = fmaxf(acc.z, 0.f); acc.w = fmaxf(acc.w, 0.f);
    __nv_bfloat16 h0 = __float2bfloat16_rn(acc.x);
    __nv_bfloat16 h1b = __float2bfloat16_rn(acc.y);
    __nv_bfloat16 h2 = __float2bfloat16_rn(acc.z);
    __nv_bfloat16 h3 = __float2bfloat16_rn(acc.w);
    __nv_bfloat16 l0 = __float2bfloat16_rn(acc.x - __bfloat162float(h0));
    __nv_bfloat16 l1 = __float2bfloat16_rn(acc.y - __bfloat162float(h1b));
    __nv_bfloat16 l2 = __float2bfloat16_rn(acc.z - __bfloat162float(h2));
    __nv_bfloat16 l3 = __float2bfloat16_rn(acc.w - __bfloat162float(h3));
    *(uint2*)(ohi + base) = make_uint2(pk_bf16x2(h0, h1b), pk_bf16x2(h2, h3));
    *(uint2*)(olo + base) = make_uint2(pk_bf16x2(l0, l1), pk_bf16x2(l2, l3));
}

// ---------------- GAT scores (batched) ----------------
__global__ void gat_asad_kernel(const float* __restrict__ hg, const float* __restrict__ asrc,
                                const float* __restrict__ adst, float* __restrict__ as_,
                                float* __restrict__ ad_) {
    const int k = blockIdx.y;
    hg += (size_t)k * NN * HIDD;
    asrc += (size_t)k * HEADS * HC;
    adst += (size_t)k * HEADS * HC;
    as_ += (size_t)k * NN * HEADS;
    ad_ += (size_t)k * NN * HEADS;

    int n = blockIdx.x;
    int h = threadIdx.x >> 5, c = threadIdx.x & 31;
    float v = hg[(size_t)n * HIDD + h * HC + c];
    float s = v * asrc[h * HC + c];
    float d = v * adst[h * HC + c];
#pragma unroll
    for (int o = 16; o; o >>= 1) {
        s += __shfl_down_sync(0xffffffffu, s, o);
        d += __shfl_down_sync(0xffffffffu, d, o);
    }
    if (c == 0) {
        as_[n * HEADS + h] = s;
        ad_[n * HEADS + h] = d;
    }
}

// ---------------- GAT gather + softmax + LN (batched; edge loops unrolled x4) ----------------
__global__ void gat_gather_ln_kernel(const float* __restrict__ hg, const int* __restrict__ csr,
                                     const int* __restrict__ off, const float* __restrict__ as_,
                                     const float* __restrict__ ad_, const float* __restrict__ ab,
                                     const float* __restrict__ lg, const float* __restrict__ lb,
                                     float* __restrict__ outp) {
    const int k = blockIdx.y;
    const size_t NH = (size_t)NN * HIDD;
    hg += (size_t)k * NH;
    csr += (size_t)k * EDGES;
    off += (size_t)k * (NN + 1);
    as_ += (size_t)k * NN * HEADS;
    ad_ += (size_t)k * NN * HEADS;
    ab += (size_t)k * HIDD;
    lg += (size_t)k * HIDD;
    lb += (size_t)k * HIDD;
    outp += (size_t)k * NH;

    int n = blockIdx.x, c = threadIdx.x, h = c >> 5;
    int beg = __ldg(&off[n]), end = __ldg(&off[n + 1]);
    float adn = __ldg(&ad_[n * HEADS + h]);
    float eself = lrelu(__ldg(&as_[n * HEADS + h]) + adn);

    float m = eself;
    {
        int j = beg;
        for (; j + 4 <= end; j += 4) {
            int s0 = __ldg(&csr[j + 0]);
            int s1 = __ldg(&csr[j + 1]);
            int s2 = __ldg(&csr[j + 2]);
            int s3 = __ldg(&csr[j + 3]);
            float e0 = lrelu(__ldg(&as_[s0 * HEADS + h]) + adn);
            float e1 = lrelu(__ldg(&as_[s1 * HEADS + h]) + adn);
            float e2 = lrelu(__ldg(&as_[s2 * HEADS + h]) + adn);
            float e3 = lrelu(__ldg(&as_[s3 * HEADS + h]) + adn);
            m = fmaxf(m, fmaxf(fmaxf(e0, e1), fmaxf(e2, e3)));
        }
        for (; j < end; j++) {
            int s = __ldg(&csr[j]);
            m = fmaxf(m, lrelu(__ldg(&as_[s * HEADS + h]) + adn));
        }
    }

    float denom = expf(eself - m);
    float acc = hg[(size_t)n * HIDD + c] * denom;
    {
        int j = beg;
        for (; j + 4 <= end; j += 4) {
            int s0 = __ldg(&csr[j + 0]);
            int s1 = __ldg(&csr[j + 1]);
            int s2 = __ldg(&csr[j + 2]);
            int s3 = __ldg(&csr[j + 3]);
            float w0 = expf(lrelu(__ldg(&as_[s0 * HEADS + h]) + adn) - m);
            float w1 = expf(lrelu(__ldg(&as_[s1 * HEADS + h]) + adn) - m);
            float w2 = expf(lrelu(__ldg(&as_[s2 * HEADS + h]) + adn) - m);
            float w3 = expf(lrelu(__ldg(&as_[s3 * HEADS + h]) + adn) - m);
            float g0 = hg[(size_t)s0 * HIDD + c];
            float g1 = hg[(size_t)s1 * HIDD + c];
            float g2 = hg[(size_t)s2 * HIDD + c];
            float g3 = hg[(size_t)s3 * HIDD + c];
            denom += w0; acc += g0 * w0;
            denom += w1; acc += g1 * w1;
            denom += w2; acc += g2 * w2;
            denom += w3; acc += g3 * w3;
        }
        for (; j < end; j++) {
            int s = __ldg(&csr[j]);
            float w = expf(lrelu(__ldg(&as_[s * HEADS + h]) + adn) - m);
            denom += w;
            acc += hg[(size_t)s * HIDD + c] * w;
        }
    }
    float val = acc / denom + ab[c];

    __shared__ float red[8];
    __shared__ float s_mu, s_rstd;
    float s = val;
#pragma unroll
    for (int o = 16; o; o >>= 1) s += __shfl_down_sync(0xffffffffu, s, o);
    if ((c & 31) == 0) red[c >> 5] = s;
    __syncthreads();
    if (c == 0) {
        float t = 0.f;
#pragma unroll
        for (int i = 0; i < 8; i++) t += red[i];
        s_mu = t * (1.0f / HIDD);
    }
    __syncthreads();
    float dv = val - s_mu;
    float q = dv * dv;
#pragma unroll
    for (int o = 16; o; o >>= 1) q += __shfl_down_sync(0xffffffffu, q, o);
    if ((c & 31) == 0) red[c >> 5] = q;
    __syncthreads();
    if (c == 0) {
        float t = 0.f;
#pragma unroll
        for (int i = 0; i < 8; i++) t += red[i];
        s_rstd = rsqrtf(t * (1.0f / HIDD) + LN_EPS);
    }
    __syncthreads();
    outp[(size_t)n * HIDD + c] = dv * s_rstd * lg[c] + lb[c];
}

// ---------------- fusion tail ----------------
__global__ void fuse_logits_kernel(const float* __restrict__ t, const float* __restrict__ b1,
                                   const float* __restrict__ W2, const float* __restrict__ b2,
                                   float* __restrict__ w) {
    int gw = (blockIdx.x * blockDim.x + threadIdx.x) >> 5;
    int lane = threadIdx.x & 31;
    if (gw >= NN) return;
    const float* row = t + (size_t)gw * HIDD;
    float a0 = 0.f, a1 = 0.f, a2 = 0.f, a3 = 0.f;
    for (int c = lane; c < HIDD; c += 32) {
        float tv = tanhf(row[c] + b1[c]);
        a0 += tv * W2[c * 4 + 0];
        a1 += tv * W2[c * 4 + 1];
        a2 += tv * W2[c * 4 + 2];
        a3 += tv * W2[c * 4 + 3];
    }
#pragma unroll
    for (int o = 16; o; o >>= 1) {
        a0 += __shfl_down_sync(0xffffffffu, a0, o);
        a1 += __shfl_down_sync(0xffffffffu, a1, o);
        a2 += __shfl_down_sync(0xffffffffu, a2, o);
        a3 += __shfl_down_sync(0xffffffffu, a3, o);
    }
    if (lane == 0) {
        float l0 = a0 + b2[0], l1 = a1 + b2[1], l2 = a2 + b2[2], l3 = a3 + b2[3];
        float mx = fmaxf(fmaxf(l0, l1), fmaxf(l2, l3));
        float e0 = expf(l0 - mx), e1 = expf(l1 - mx), e2 = expf(l2 - mx), e3 = expf(l3 - mx);
        float inv = 1.0f / (e0 + e1 + e2 + e3);
        w[gw * 4 + 0] = e0 * inv;
        w[gw * 4 + 1] = e1 * inv;
        w[gw * 4 + 2] = e2 * inv;
        w[gw * 4 + 3] = e3 * inv;
    }
}

__global__ void combine_kernel(const float* __restrict__ w, float* __restrict__ out) {
    int idx = blockIdx.x * 256 + threadIdx.x;
    int n = idx >> 8;
    float acc = 0.f;
#pragma unroll
    for (int k = 0; k < KK; k++) acc += w[n * KK + k] * g_outs[(size_t)k * NN * HIDD + idx];
    out[idx] = acc;
}

// ---------------- host ----------------
extern "C" void kernel_launch(void* const* d_in, const int* in_sizes, int n_in,
                              void* d_out, int out_size) {
    const float *x, *style, *stress;
    const int* ei[KK];
    int base;
    if (in_sizes[1] == 2 * EDGES) {
        x = (const float*)d_in[0];
        for (int k = 0; k < KK; k++) ei[k] = (const int*)d_in[1 + k];
        style = (const float*)d_in[5];
        stress = (const float*)d_in[6];
        base = 7;
    } else {
        x = (const float*)d_in[0];
        style = (const float*)d_in[1];
        stress = (const float*)d_in[2];
        for (int k = 0; k < KK; k++) ei[k] = (const int*)d_in[3 + k];
        base = 7;
    }
    const float* gW0 = (const float*)d_in[base + 0];
    const float* gb0 = (const float*)d_in[base + 1];
    const float* gW1 = (const float*)d_in[base + 2];
    const float* gb1 = (const float*)d_in[base + 3];
    const float* gW2 = (const float*)d_in[base + 4];
    const float* gb2 = (const float*)d_in[base + 5];
    const float* aW  = (const float*)d_in[base + 6];
    const float* aas = (const float*)d_in[base + 7];
    const float* aad = (const float*)d_in[base + 8];
    const float* ab  = (const float*)d_in[base + 9];
    const float* lg  = (const float*)d_in[base + 10];
    const float* lb  = (const float*)d_in[base + 11];
    const float* fW1 = (const float*)d_in[base + 12];
    const float* fb1 = (const float*)d_in[base + 13];
    const float* fW2 = (const float*)d_in[base + 14];
    const float* fb2 = (const float*)d_in[base + 15];

    float *h1, *hf, *outs, *dinv, *as_, *ad_, *wbuf;
    __nv_bfloat16 *hs_hi, *hs_lo, *xs_hi, *xs_lo, *st_hi, *st_lo, *bsw;
    int *counts, *off, *cursor, *bsum, *csr;
    cudaGetSymbolAddress((void**)&h1, g_h1);
    cudaGetSymbolAddress((void**)&hf, g_hf);
    cudaGetSymbolAddress((void**)&hs_hi, g_hs_hi);
    cudaGetSymbolAddress((void**)&hs_lo, g_hs_lo);
    cudaGetSymbolAddress((void**)&xs_hi, g_xs_hi);
    cudaGetSymbolAddress((void**)&xs_lo, g_xs_lo);
    cudaGetSymbolAddress((void**)&st_hi, g_st_hi);
    cudaGetSymbolAddress((void**)&st_lo, g_st_lo);
    cudaGetSymbolAddress((void**)&outs, g_outs);
    cudaGetSymbolAddress((void**)&dinv, g_dinv);
    cudaGetSymbolAddress((void**)&as_, g_as);
    cudaGetSymbolAddress((void**)&ad_, g_ad);
    cudaGetSymbolAddress((void**)&wbuf, g_w);
    cudaGetSymbolAddress((void**)&counts, g_counts);
    cudaGetSymbolAddress((void**)&off, g_off);
    cudaGetSymbolAddress((void**)&cursor, g_cursor);
    cudaGetSymbolAddress((void**)&bsum, g_bsum);
    cudaGetSymbolAddress((void**)&csr, g_csr);
    cudaGetSymbolAddress((void**)&bsw, g_bsplit);

    cudaFuncSetAttribute(gemm_tc_kernel, cudaFuncAttributeMaxDynamicSharedMemorySize, GEMM_SMEM);

    const size_t TOPO = 655360, OW1 = 262144, OW2 = 393216, OAW = 524288, OFUS = 2621440;
    const size_t NH = (size_t)NN * HIDD;
    dim3 ggridK5(2, cdiv(NN, 128), KK + 1);  // L0 GEMMs + fusion GEMM
    dim3 ggridK(2, cdiv(NN, 128), KK);
    dim3 egridK(cdiv(EDGES, 256), KK);
    dim3 sgridK(SCAN_BLOCKS, KK);
    dim3 ngridK(NN / 4, KK);
    dim3 agridK(NN, KK);

    // startup
    bsplit_all_kernel<<<dim3(512, 17), 256>>>(gW0, gW1, gW2, aW, fW1, bsw);
    zero_int_kernel<<<cdiv(KK * NN, 256), 256>>>(counts, KK * NN);
    split_act_kernel<<<cdiv(NN * IN_DIM, 256), 256>>>(x, xs_hi, xs_lo, NN, IN_DIM, IN_DIM, 0);
    split_act_kernel<<<cdiv(NN * HIDD, 256), 256>>>(style, st_hi, st_lo, NN, HIDD, IN_DIM, 0);
    split_act_kernel<<<cdiv(NN * HIDD, 256), 256>>>(stress, st_hi, st_lo, NN, HIDD, IN_DIM, HIDD);

    // GCN L0 GEMMs (z<4) + fusion GEMM (z==4) in one launch; all K=512
    gemm_tc_kernel<<<ggridK5, 256, GEMM_SMEM>>>(xs_hi, xs_lo, 0, IN_DIM,
                                                bsw, TOPO, h1, NH, NN, IN_DIM, KK,
                                                st_hi, st_lo, bsw + OFUS, hf);

    // CSR build (all topologies)
    hist_kernel<<<egridK, 256>>>(ei[0], ei[1], ei[2], ei[3], counts);
    scanA_kernel<<<sgridK, 1024>>>(counts, off, bsum);
    scanC_kernel<<<sgridK, 1024>>>(counts, off, cursor, bsum, dinv);
    fillcsr_kernel<<<egridK, 256>>>(ei[0], ei[1], ei[2], ei[3], cursor, csr);

    gcn_gather_kernel<<<ngridK, 256>>>(h1, csr, off, dinv, gb0, hs_hi, hs_lo);

    gemm_tc_kernel<<<ggridK, 256, GEMM_SMEM>>>(hs_hi, hs_lo, NH, HIDD,
                                               bsw + OW1, TOPO, h1, NH, NN, HIDD, -1,
                                               nullptr, nullptr, nullptr, nullptr);
    gcn_gather_kernel<<<ngridK, 256>>>(h1, csr, off, dinv, gb1, hs_hi, hs_lo);

    gemm_tc_kernel<<<ggridK, 256, GEMM_SMEM>>>(hs_hi, hs_lo, NH, HIDD,
                                               bsw + OW2, TOPO, h1, NH, NN, HIDD, -1,
                                               nullptr, nullptr, nullptr, nullptr);
    gcn_gather_kernel<<<ngridK, 256>>>(h1, csr, off, dinv, gb2, hs_hi, hs_lo);

    gemm_tc_kernel<<<ggridK, 256, GEMM_SMEM>>>(hs_hi, hs_lo, NH, HIDD,
                                               bsw + OAW, TOPO, h1, NH, NN, HIDD, -1,
                                               nullptr, nullptr, nullptr, nullptr);
    gat_asad_kernel<<<agridK, 256>>>(h1, aas, aad, as_, ad_);
    gat_gather_ln_kernel<<<agridK, 256>>>(h1, csr, off, as_, ad_, ab, lg, lb, outs);

    // fusion tail (GEMM already done in the L0 launch)
    fuse_logits_kernel<<<cdiv(NN * 32, 256), 256>>>(hf, fb1, fW2, fb2, wbuf);
    combine_kernel<<<NN, 256>>>(wbuf, (float*)d_out);
}

// round 16
// speedup vs baseline: 1.2001x; 1.1395x over previous
#include <cuda_runtime.h>
#include <cuda_bf16.h>
#include <math.h>
#include <stdint.h>

#define NN 50000
#define IN_DIM 512
#define HIDD 256
#define HEADS 8
#define HC 32
#define EDGES 600000
#define KK 4
#define LN_EPS 1e-5f
#define SCAN_BLOCKS 49

// ---------------- scratch (per-topology) ----------------
__device__ float g_h1[KK * NN * HIDD];
__device__ float g_hf[NN * HIDD];
__device__ __nv_bfloat16 g_hs_hi[KK * NN * HIDD];
__device__ __nv_bfloat16 g_hs_lo[KK * NN * HIDD];
__device__ __nv_bfloat16 g_xs_hi[NN * IN_DIM];
__device__ __nv_bfloat16 g_xs_lo[NN * IN_DIM];
__device__ __nv_bfloat16 g_st_hi[NN * IN_DIM];
__device__ __nv_bfloat16 g_st_lo[NN * IN_DIM];
__device__ float g_outs[KK * NN * HIDD];
__device__ float g_dinv[KK * NN];
__device__ float g_as[KK * NN * HEADS];
__device__ float g_ad[KK * NN * HEADS];
__device__ float g_w[NN * KK];
__device__ int g_counts[KK * NN];
__device__ int g_off[KK * (NN + 1)];
__device__ int g_cursor[KK * NN];
__device__ int g_bsum[KK * SCAN_BLOCKS];
__device__ int g_csr[KK * EDGES];
__device__ __nv_bfloat16 g_bsplit[88 * 32768];

__device__ __forceinline__ float lrelu(float x) { return x > 0.f ? x : 0.2f * x; }
static inline int cdiv(int a, int b) { return (a + b - 1) / b; }

__device__ __forceinline__ uint32_t pk_bf16x2(__nv_bfloat16 a, __nv_bfloat16 b) {
    return (uint32_t)__bfloat16_as_ushort(a) | ((uint32_t)__bfloat16_as_ushort(b) << 16);
}

__device__ __forceinline__ void mma16816(float* c, const uint32_t* a, const uint32_t* b) {
    asm volatile(
        "mma.sync.aligned.m16n8k16.row.col.f32.bf16.bf16.f32 "
        "{%0,%1,%2,%3}, {%4,%5,%6,%7}, {%8,%9}, {%0,%1,%2,%3};"
        : "+f"(c[0]), "+f"(c[1]), "+f"(c[2]), "+f"(c[3])
        : "r"(a[0]), "r"(a[1]), "r"(a[2]), "r"(a[3]), "r"(b[0]), "r"(b[1]));
}

#define LDSM4(r, addr) \
    asm volatile("ldmatrix.sync.aligned.m8n8.x4.shared.b16 {%0,%1,%2,%3}, [%4];" \
                 : "=r"((r)[0]), "=r"((r)[1]), "=r"((r)[2]), "=r"((r)[3]) : "r"(addr))

__device__ __forceinline__ void cp16(uint32_t saddr, const void* gptr, bool pred) {
    int sz = pred ? 16 : 0;
    asm volatile("cp.async.cg.shared.global [%0], [%1], 16, %2;"
                 :: "r"(saddr), "l"(gptr), "r"(sz) : "memory");
}

// ---------------- weight split (all matrices, one launch) ----------------
__global__ void bsplit_all_kernel(const float* __restrict__ gW0, const float* __restrict__ gW1,
                                  const float* __restrict__ gW2, const float* __restrict__ aW,
                                  const float* __restrict__ fW1, __nv_bfloat16* __restrict__ bsw) {
    int seg = blockIdx.y;
    const float* src;
    __nv_bfloat16* dst;
    int total;
    if (seg == 16) {
        src = fW1; dst = bsw + 2621440; total = 512 * 256;
    } else {
        int topo = seg >> 2, which = seg & 3;
        __nv_bfloat16* tb = bsw + (size_t)topo * 655360;
        if (which == 0)      { src = gW0 + (size_t)topo * 512 * 256; dst = tb;          total = 512 * 256; }
        else if (which == 1) { src = gW1 + (size_t)topo * 256 * 256; dst = tb + 262144; total = 256 * 256; }
        else if (which == 2) { src = gW2 + (size_t)topo * 256 * 256; dst = tb + 393216; total = 256 * 256; }
        else                 { src = aW  + (size_t)topo * 256 * 256; dst = tb + 524288; total = 256 * 256; }
    }
    int idx = blockIdx.x * 256 + threadIdx.x;
    if (idx >= total) return;
    int kk = idx >> 8;
    int n = idx & 255;
    float w = src[idx];
    __nv_bfloat16 hi = __float2bfloat16_rn(w);
    __nv_bfloat16 lo = __float2bfloat16_rn(w - __bfloat162float(hi));
    int chunk = kk >> 5, kin = kk & 31;
    __nv_bfloat16* base = dst + (size_t)chunk * 16384;
    base[n * 32 + kin] = hi;
    base[n * 32 + kin + 8192] = lo;
}

// ---------------- activation split ----------------
__global__ void split_act_kernel(const float* __restrict__ src, __nv_bfloat16* __restrict__ dhi,
                                 __nv_bfloat16* __restrict__ dlo, int rows, int cols,
                                 int dst_ld, int dst_off) {
    int idx = blockIdx.x * 256 + threadIdx.x;
    if (idx >= rows * cols) return;
    int r = idx / cols, c = idx - r * cols;
    float v = src[idx];
    __nv_bfloat16 hi = __float2bfloat16_rn(v);
    __nv_bfloat16 lo = __float2bfloat16_rn(v - __bfloat162float(hi));
    size_t o = (size_t)r * dst_ld + dst_off + c;
    dhi[o] = hi;
    dlo[o] = lo;
}

// ---------------- CSR build (batched over topology via blockIdx.y) ----------------
__global__ void zero_int_kernel(int* p, int n) {
    int i = blockIdx.x * 256 + threadIdx.x;
    if (i < n) p[i] = 0;
}

__global__ void hist_kernel(const int* __restrict__ e0, const int* __restrict__ e1,
                            const int* __restrict__ e2, const int* __restrict__ e3,
                            int* __restrict__ counts) {
    int k = blockIdx.y;
    const int* dst = (k == 0 ? e0 : k == 1 ? e1 : k == 2 ? e2 : e3) + EDGES;
    int i = blockIdx.x * 256 + threadIdx.x;
    if (i < EDGES) atomicAdd(&counts[k * NN + dst[i]], 1);
}

__global__ void scanA_kernel(const int* __restrict__ counts, int* __restrict__ scanbuf,
                             int* __restrict__ bsum) {
    int k = blockIdx.y;
    counts += (size_t)k * NN;
    scanbuf += (size_t)k * (NN + 1);
    bsum += (size_t)k * SCAN_BLOCKS;
    __shared__ int sh[1024];
    int b = blockIdx.x, t = threadIdx.x;
    int i = b * 1024 + t;
    int v = (i < NN) ? counts[i] : 0;
    sh[t] = v;
    __syncthreads();
#pragma unroll
    for (int o = 1; o < 1024; o <<= 1) {
        int x = (t >= o) ? sh[t - o] : 0;
        __syncthreads();
        sh[t] += x;
        __syncthreads();
    }
    if (i < NN) scanbuf[i] = sh[t];
    if (t == 1023) bsum[b] = sh[t];
}

__global__ void scanC_kernel(const int* __restrict__ counts, int* __restrict__ off,
                             int* __restrict__ cursor, const int* __restrict__ bsum,
                             float* __restrict__ dinv) {
    int k = blockIdx.y;
    counts += (size_t)k * NN;
    off += (size_t)k * (NN + 1);
    cursor += (size_t)k * NN;
    bsum += (size_t)k * SCAN_BLOCKS;
    dinv += (size_t)k * NN;
    int b = blockIdx.x, t = threadIdx.x;
    int i = b * 1024 + t;
    if (i >= NN) return;
    int prefix = 0;
    for (int j = 0; j < b; j++) prefix += bsum[j];
    int cnt = counts[i];
    int excl = off[i] - cnt + prefix;
    off[i] = excl;
    cursor[i] = excl;
    dinv[i] = rsqrtf((float)cnt + 1.0f);
    if (i == NN - 1) off[NN] = excl + cnt;
}

__global__ void fillcsr_kernel(const int* __restrict__ e0, const int* __restrict__ e1,
                               const int* __restrict__ e2, const int* __restrict__ e3,
                               int* __restrict__ cursor, int* __restrict__ csr) {
    int k = blockIdx.y;
    const int* ep = (k == 0 ? e0 : k == 1 ? e1 : k == 2 ? e2 : e3);
    const int* src = ep;
    const int* dst = ep + EDGES;
    cursor += (size_t)k * NN;
    csr += (size_t)k * EDGES;
    int i = blockIdx.x * 256 + threadIdx.x;
    if (i >= EDGES) return;
    int pos = atomicAdd(&cursor[dst[i]], 1);
    csr[pos] = src[i];
}

// ---------------- tensor-core GEMM, batched over blockIdx.z; single barrier per chunk ----------------
// Optional fused GAT score epilogue: if asrc != null, also writes
// as_[row*HEADS+head] = sum_c C[row, head*32+c]*asrc[head*32+c] (and ad_ with adst).
#define SA 40
#define STAGE_BYTES 40960
#define GEMM_SMEM (2 * STAGE_BYTES)

__global__ void __launch_bounds__(256, 2)
gemm_tc_kernel(const __nv_bfloat16* __restrict__ Ahi, const __nv_bfloat16* __restrict__ Alo,
               size_t strideA, int lda,
               const __nv_bfloat16* __restrict__ Bsw, size_t strideB,
               float* __restrict__ C, size_t strideC, int M, int Kd, int zAlt,
               const __nv_bfloat16* __restrict__ A2hi, const __nv_bfloat16* __restrict__ A2lo,
               const __nv_bfloat16* __restrict__ B2, float* __restrict__ C2,
               const float* __restrict__ asrc, const float* __restrict__ adst,
               float* __restrict__ as_out, float* __restrict__ ad_out) {
    extern __shared__ char smem[];
    const uint32_t sbase = (uint32_t)__cvta_generic_to_shared(smem);

    const int z = blockIdx.z;
    if (z == zAlt) {
        Ahi = A2hi; Alo = A2lo; Bsw = B2; C = C2;
    } else {
        Ahi += (size_t)z * strideA;
        Alo += (size_t)z * strideA;
        Bsw += (size_t)z * strideB;
        C += (size_t)z * strideC;
    }
    if (asrc) {
        asrc += (size_t)z * HEADS * HC;
        adst += (size_t)z * HEADS * HC;
        as_out += (size_t)z * NN * HEADS;
        ad_out += (size_t)z * NN * HEADS;
    }

    const int tid = threadIdx.x;
    const int wid = tid >> 5;
    const int lane = tid & 31;
    const int g = lane >> 2;
    const int tig = lane & 3;

    const int rowBase = blockIdx.y * 128;
    const int colBase = blockIdx.x * 128;
    const int warp_m = (wid >> 2) * 64;
    const int warp_n = (wid & 3) * 32;

    const int srow = tid >> 1;
    const int shalf = tid & 1;
    const int rg = rowBase + srow;
    const bool rok = (rg < M);

    float acc[4][4][4];
#pragma unroll
    for (int i = 0; i < 4; i++)
#pragma unroll
        for (int j = 0; j < 4; j++)
#pragma unroll
            for (int q = 0; q < 4; q++) acc[i][j][q] = 0.f;

    const uint32_t soff = (srow * SA + shalf * 16) * 2;
    const uint32_t a_loff = (uint32_t)(warp_m + (lane & 15)) * (SA * 2) + ((lane & 16) ? 16 : 0);
    const uint32_t b_loff = (uint32_t)(warp_n + (lane & 7) + ((lane & 16) ? 8 : 0)) * (SA * 2)
                          + ((lane & 8) ? 16 : 0);

    auto stage_load = [&](int c, int s) {
        uint32_t st = sbase + s * STAGE_BYTES;
        size_t go = (size_t)rg * lda + (c << 5) + shalf * 16;
        cp16(st + soff,              Ahi + go,     rok);
        cp16(st + soff + 16,         Ahi + go + 8, rok);
        cp16(st + 10240 + soff,      Alo + go,     rok);
        cp16(st + 10240 + soff + 16, Alo + go + 8, rok);
        const __nv_bfloat16* Bc = Bsw + (size_t)c * 16384 + (size_t)(colBase + srow) * 32 + shalf * 16;
        cp16(st + 20480 + soff,      Bc,        true);
        cp16(st + 20480 + soff + 16, Bc + 8,    true);
        cp16(st + 30720 + soff,      Bc + 8192, true);
        cp16(st + 30720 + soff + 16, Bc + 8200, true);
    };

    const int nChunks = Kd >> 5;
    stage_load(0, 0);
    asm volatile("cp.async.commit_group;" ::: "memory");

    for (int c = 0; c < nChunks; c++) {
        asm volatile("cp.async.wait_group 0;" ::: "memory");
        __syncthreads();
        if (c + 1 < nChunks) {
            stage_load(c + 1, (c + 1) & 1);
            asm volatile("cp.async.commit_group;" ::: "memory");
        }

        const uint32_t st = sbase + (c & 1) * STAGE_BYTES;

#pragma unroll
        for (int ks = 0; ks < 2; ks++) {
            const uint32_t kb = ks * 32;
            uint32_t ah[4][4], al[4][4];
#pragma unroll
            for (int mt = 0; mt < 4; mt++) {
                uint32_t ad = st + a_loff + mt * (16 * SA * 2) + kb;
                LDSM4(ah[mt], ad);
                LDSM4(al[mt], ad + 10240);
            }
            uint32_t bh[4][2], bl[4][2];
#pragma unroll
            for (int p = 0; p < 2; p++) {
                uint32_t bd = st + 20480 + b_loff + p * (16 * SA * 2) + kb;
                uint32_t t4[4];
                LDSM4(t4, bd);
                bh[2 * p][0] = t4[0]; bh[2 * p][1] = t4[1];
                bh[2 * p + 1][0] = t4[2]; bh[2 * p + 1][1] = t4[3];
                LDSM4(t4, bd + 10240);
                bl[2 * p][0] = t4[0]; bl[2 * p][1] = t4[1];
                bl[2 * p + 1][0] = t4[2]; bl[2 * p + 1][1] = t4[3];
            }
#pragma unroll
            for (int mt = 0; mt < 4; mt++)
#pragma unroll
                for (int nt = 0; nt < 4; nt++) {
                    mma16816(acc[mt][nt], ah[mt], bh[nt]);
                    mma16816(acc[mt][nt], ah[mt], bl[nt]);
                    mma16816(acc[mt][nt], al[mt], bh[nt]);
                }
        }
    }

#pragma unroll
    for (int mt = 0; mt < 4; mt++) {
        int row0 = rowBase + warp_m + mt * 16 + g;
        int row1 = row0 + 8;
#pragma unroll
        for (int nt = 0; nt < 4; nt++) {
            int col = colBase + warp_n + nt * 8 + tig * 2;
            if (row0 < M)
                *(float2*)(C + (size_t)row0 * 256 + col) = make_float2(acc[mt][nt][0], acc[mt][nt][1]);
            if (row1 < M)
                *(float2*)(C + (size_t)row1 * 256 + col) = make_float2(acc[mt][nt][2], acc[mt][nt][3]);
        }
    }

    // fused GAT per-node head scores: this warp's 32 cols = one head
    if (asrc) {
        const int head = (colBase + warp_n) >> 5;
#pragma unroll
        for (int mt = 0; mt < 4; mt++) {
            float s0 = 0.f, d0 = 0.f, s1 = 0.f, d1 = 0.f;
#pragma unroll
            for (int nt = 0; nt < 4; nt++) {
                int lc = nt * 8 + tig * 2;
                float a0 = asrc[head * HC + lc], a1 = asrc[head * HC + lc + 1];
                float b0 = adst[head * HC + lc], b1 = adst[head * HC + lc + 1];
                s0 += acc[mt][nt][0] * a0 + acc[mt][nt][1] * a1;
                d0 += acc[mt][nt][0] * b0 + acc[mt][nt][1] * b1;
                s1 += acc[mt][nt][2] * a0 + acc[mt][nt][3] * a1;
                d1 += acc[mt][nt][2] * b0 + acc[mt][nt][3] * b1;
            }
            // reduce over tig (quad)
            s0 += __shfl_xor_sync(0xffffffffu, s0, 1); s0 += __shfl_xor_sync(0xffffffffu, s0, 2);
            d0 += __shfl_xor_sync(0xffffffffu, d0, 1); d0 += __shfl_xor_sync(0xffffffffu, d0, 2);
            s1 += __shfl_xor_sync(0xffffffffu, s1, 1); s1 += __shfl_xor_sync(0xffffffffu, s1, 2);
            d1 += __shfl_xor_sync(0xffffffffu, d1, 1); d1 += __shfl_xor_sync(0xffffffffu, d1, 2);
            int row0 = rowBase + warp_m + mt * 16 + g;
            int row1 = row0 + 8;
            if (tig == 0) {
                if (row0 < M) { as_out[row0 * HEADS + head] = s0; ad_out[row0 * HEADS + head] = d0; }
                if (row1 < M) { as_out[row1 * HEADS + head] = s1; ad_out[row1 * HEADS + head] = d1; }
            }
        }
    }
}

// ---------------- GCN gather (batched over blockIdx.y; edge loop unrolled x4) ----------------
__global__ void gcn_gather_kernel(const float* __restrict__ h, const int* __restrict__ csr,
                                  const int* __restrict__ off, const float* __restrict__ dinv,
                                  const float* __restrict__ bias,
                                  __nv_bfloat16* __restrict__ ohi, __nv_bfloat16* __restrict__ olo) {
    const int k = blockIdx.y;
    const size_t NH = (size_t)NN * HIDD;
    h += (size_t)k * NH;
    csr += (size_t)k * EDGES;
    off += (size_t)k * (NN + 1);
    dinv += (size_t)k * NN;
    bias += (size_t)k * HIDD;
    ohi += (size_t)k * NH;
    olo += (size_t)k * NH;

    int tid = threadIdx.x;
    int n = blockIdx.x * 4 + (tid >> 6);
    int t = tid & 63;
    size_t base = (size_t)n * HIDD + t * 4;
    float dn = dinv[n];
    float dn2 = dn * dn;
    float4 hv = *(const float4*)(h + base);
    float4 bv = *(const float4*)(bias + t * 4);
    float4 acc = make_float4(hv.x * dn2 + bv.x, hv.y * dn2 + bv.y,
                             hv.z * dn2 + bv.z, hv.w * dn2 + bv.w);
    int beg = __ldg(&off[n]), end = __ldg(&off[n + 1]);
    int j = beg;
    for (; j + 4 <= end; j += 4) {
        int s0 = __ldg(&csr[j + 0]);
        int s1 = __ldg(&csr[j + 1]);
        int s2 = __ldg(&csr[j + 2]);
        int s3 = __ldg(&csr[j + 3]);
        float c0 = __ldg(&dinv[s0]) * dn;
        float c1 = __ldg(&dinv[s1]) * dn;
        float c2 = __ldg(&dinv[s2]) * dn;
        float c3 = __ldg(&dinv[s3]) * dn;
        float4 v0 = *(const float4*)(h + (size_t)s0 * HIDD + t * 4);
        float4 v1 = *(const float4*)(h + (size_t)s1 * HIDD + t * 4);
        float4 v2 = *(const float4*)(h + (size_t)s2 * HIDD + t * 4);
        float4 v3 = *(const float4*)(h + (size_t)s3 * HIDD + t * 4);
        acc.x += v0.x * c0; acc.y += v0.y * c0; acc.z += v0.z * c0; acc.w += v0.w * c0;
        acc.x += v1.x * c1; acc.y += v1.y * c1; acc.z += v1.z * c1; acc.w += v1.w * c1;
        acc.x += v2.x * c2; acc.y += v2.y * c2; acc.z += v2.z * c2; acc.w += v2.w * c2;
        acc.x += v3.x * c3; acc.y += v3.y * c3; acc.z += v3.z * c3; acc.w += v3.w * c3;
    }
    for (; j < end; j++) {
        int s = __ldg(&csr[j]);
        float cf = __ldg(&dinv[s]) * dn;
        float4 v = *(const float4*)(h + (size_t)s * HIDD + t * 4);
        acc.x += v.x * cf; acc.y += v.y * cf; acc.z += v.z * cf; acc.w += v.w * cf;
    }
    acc.x = fmaxf(acc.x, 0.f); acc.y = fmaxf(acc.y, 0.f);
    acc.z = fmaxf(acc.z, 0.f); acc.w = fmaxf(acc.w, 0.f);
    __nv_bfloat16 h0 = __float2bfloat16_rn(acc.x);
    __nv_bfloat16 h1b = __float2bfloat16_rn(acc.y);
    __nv_bfloat16 h2 = __float2bfloat16_rn(acc.z);
    __nv_bfloat16 h3 = __float2bfloat16_rn(acc.w);
    __nv_bfloat16 l0 = __float2bfloat16_rn(acc.x - __bfloat162float(h0));
    __nv_bfloat16 l1 = __float2bfloat16_rn(acc.y - __bfloat162float(h1b));
    __nv_bfloat16 l2 = __float2bfloat16_rn(acc.z - __bfloat162float(h2));
    __nv_bfloat16 l3 = __float2bfloat16_rn(acc.w - __bfloat162float(h3));
    *(uint2*)(ohi + base) = make_uint2(pk_bf16x2(h0, h1b), pk_bf16x2(h2, h3));
    *(uint2*)(olo + base) = make_uint2(pk_bf16x2(l0, l1), pk_bf16x2(l2, l3));
}

// ---------------- GAT gather + one-pass softmax (self-score reference) + LN ----------------
__global__ void gat_gather_ln_kernel(const float* __restrict__ hg, const int* __restrict__ csr,
                                     const int* __restrict__ off, const float* __restrict__ as_,
                                     const float* __restrict__ ad_, const float* __restrict__ ab,
                                     const float* __restrict__ lg, const float* __restrict__ lb,
                                     float* __restrict__ outp) {
    const int k = blockIdx.y;
    const size_t NH = (size_t)NN * HIDD;
    hg += (size_t)k * NH;
    csr += (size_t)k * EDGES;
    off += (size_t)k * (NN + 1);
    as_ += (size_t)k * NN * HEADS;
    ad_ += (size_t)k * NN * HEADS;
    ab += (size_t)k * HIDD;
    lg += (size_t)k * HIDD;
    lb += (size_t)k * HIDD;
    outp += (size_t)k * NH;

    int n = blockIdx.x, c = threadIdx.x, h = c >> 5;
    int beg = __ldg(&off[n]), end = __ldg(&off[n + 1]);
    float adn = __ldg(&ad_[n * HEADS + h]);
    // softmax reference point = self score (mathematically identical result)
    float m = lrelu(__ldg(&as_[n * HEADS + h]) + adn);

    float denom = 1.0f;   // exp(eself - m) = 1
    float acc = hg[(size_t)n * HIDD + c];
    {
        int j = beg;
        for (; j + 4 <= end; j += 4) {
            int s0 = __ldg(&csr[j + 0]);
            int s1 = __ldg(&csr[j + 1]);
            int s2 = __ldg(&csr[j + 2]);
            int s3 = __ldg(&csr[j + 3]);
            float w0 = expf(lrelu(__ldg(&as_[s0 * HEADS + h]) + adn) - m);
            float w1 = expf(lrelu(__ldg(&as_[s1 * HEADS + h]) + adn) - m);
            float w2 = expf(lrelu(__ldg(&as_[s2 * HEADS + h]) + adn) - m);
            float w3 = expf(lrelu(__ldg(&as_[s3 * HEADS + h]) + adn) - m);
            float g0 = hg[(size_t)s0 * HIDD + c];
            float g1 = hg[(size_t)s1 * HIDD + c];
            float g2 = hg[(size_t)s2 * HIDD + c];
            float g3 = hg[(size_t)s3 * HIDD + c];
            denom += w0; acc += g0 * w0;
            denom += w1; acc += g1 * w1;
            denom += w2; acc += g2 * w2;
            denom += w3; acc += g3 * w3;
        }
        for (; j < end; j++) {
            int s = __ldg(&csr[j]);
            float w = expf(lrelu(__ldg(&as_[s * HEADS + h]) + adn) - m);
            denom += w;
            acc += hg[(size_t)s * HIDD + c] * w;
        }
    }
    float val = acc / denom + ab[c];

    __shared__ float red[8];
    __shared__ float s_mu, s_rstd;
    float s = val;
#pragma unroll
    for (int o = 16; o; o >>= 1) s += __shfl_down_sync(0xffffffffu, s, o);
    if ((c & 31) == 0) red[c >> 5] = s;
    __syncthreads();
    if (c == 0) {
        float t = 0.f;
#pragma unroll
        for (int i = 0; i < 8; i++) t += red[i];
        s_mu = t * (1.0f / HIDD);
    }
    __syncthreads();
    float dv = val - s_mu;
    float q = dv * dv;
#pragma unroll
    for (int o = 16; o; o >>= 1) q += __shfl_down_sync(0xffffffffu, q, o);
    if ((c & 31) == 0) red[c >> 5] = q;
    __syncthreads();
    if (c == 0) {
        float t = 0.f;
#pragma unroll
        for (int i = 0; i < 8; i++) t += red[i];
        s_rstd = rsqrtf(t * (1.0f / HIDD) + LN_EPS);
    }
    __syncthreads();
    outp[(size_t)n * HIDD + c] = dv * s_rstd * lg[c] + lb[c];
}

// ---------------- fusion tail ----------------
__global__ void fuse_logits_kernel(const float* __restrict__ t, const float* __restrict__ b1,
                                   const float* __restrict__ W2, const float* __restrict__ b2,
                                   float* __restrict__ w) {
    int gw = (blockIdx.x * blockDim.x + threadIdx.x) >> 5;
    int lane = threadIdx.x & 31;
    if (gw >= NN) return;
    const float* row = t + (size_t)gw * HIDD;
    float a0 = 0.f, a1 = 0.f, a2 = 0.f, a3 = 0.f;
    for (int c = lane; c < HIDD; c += 32) {
        float tv = tanhf(row[c] + b1[c]);
        a0 += tv * W2[c * 4 + 0];
        a1 += tv * W2[c * 4 + 1];
        a2 += tv * W2[c * 4 + 2];
        a3 += tv * W2[c * 4 + 3];
    }
#pragma unroll
    for (int o = 16; o; o >>= 1) {
        a0 += __shfl_down_sync(0xffffffffu, a0, o);
        a1 += __shfl_down_sync(0xffffffffu, a1, o);
        a2 += __shfl_down_sync(0xffffffffu, a2, o);
        a3 += __shfl_down_sync(0xffffffffu, a3, o);
    }
    if (lane == 0) {
        float l0 = a0 + b2[0], l1 = a1 + b2[1], l2 = a2 + b2[2], l3 = a3 + b2[3];
        float mx = fmaxf(fmaxf(l0, l1), fmaxf(l2, l3));
        float e0 = expf(l0 - mx), e1 = expf(l1 - mx), e2 = expf(l2 - mx), e3 = expf(l3 - mx);
        float inv = 1.0f / (e0 + e1 + e2 + e3);
        w[gw * 4 + 0] = e0 * inv;
        w[gw * 4 + 1] = e1 * inv;
        w[gw * 4 + 2] = e2 * inv;
        w[gw * 4 + 3] = e3 * inv;
    }
}

__global__ void combine_kernel(const float* __restrict__ w, float* __restrict__ out) {
    int idx = blockIdx.x * 256 + threadIdx.x;
    int n = idx >> 8;
    float acc = 0.f;
#pragma unroll
    for (int k = 0; k < KK; k++) acc += w[n * KK + k] * g_outs[(size_t)k * NN * HIDD + idx];
    out[idx] = acc;
}

// ---------------- host ----------------
extern "C" void kernel_launch(void* const* d_in, const int* in_sizes, int n_in,
                              void* d_out, int out_size) {
    const float *x, *style, *stress;
    const int* ei[KK];
    int base;
    if (in_sizes[1] == 2 * EDGES) {
        x = (const float*)d_in[0];
        for (int k = 0; k < KK; k++) ei[k] = (const int*)d_in[1 + k];
        style = (const float*)d_in[5];
        stress = (const float*)d_in[6];
        base = 7;
    } else {
        x = (const float*)d_in[0];
        style = (const float*)d_in[1];
        stress = (const float*)d_in[2];
        for (int k = 0; k < KK; k++) ei[k] = (const int*)d_in[3 + k];
        base = 7;
    }
    const float* gW0 = (const float*)d_in[base + 0];
    const float* gb0 = (const float*)d_in[base + 1];
    const float* gW1 = (const float*)d_in[base + 2];
    const float* gb1 = (const float*)d_in[base + 3];
    const float* gW2 = (const float*)d_in[base + 4];
    const float* gb2 = (const float*)d_in[base + 5];
    const float* aW  = (const float*)d_in[base + 6];
    const float* aas = (const float*)d_in[base + 7];
    const float* aad = (const float*)d_in[base + 8];
    const float* ab  = (const float*)d_in[base + 9];
    const float* lg  = (const float*)d_in[base + 10];
    const float* lb  = (const float*)d_in[base + 11];
    const float* fW1 = (const float*)d_in[base + 12];
    const float* fb1 = (const float*)d_in[base + 13];
    const float* fW2 = (const float*)d_in[base + 14];
    const float* fb2 = (const float*)d_in[base + 15];

    float *h1, *hf, *outs, *dinv, *as_, *ad_, *wbuf;
    __nv_bfloat16 *hs_hi, *hs_lo, *xs_hi, *xs_lo, *st_hi, *st_lo, *bsw;
    int *counts, *off, *cursor, *bsum, *csr;
    cudaGetSymbolAddress((void**)&h1, g_h1);
    cudaGetSymbolAddress((void**)&hf, g_hf);
    cudaGetSymbolAddress((void**)&hs_hi, g_hs_hi);
    cudaGetSymbolAddress((void**)&hs_lo, g_hs_lo);
    cudaGetSymbolAddress((void**)&xs_hi, g_xs_hi);
    cudaGetSymbolAddress((void**)&xs_lo, g_xs_lo);
    cudaGetSymbolAddress((void**)&st_hi, g_st_hi);
    cudaGetSymbolAddress((void**)&st_lo, g_st_lo);
    cudaGetSymbolAddress((void**)&outs, g_outs);
    cudaGetSymbolAddress((void**)&dinv, g_dinv);
    cudaGetSymbolAddress((void**)&as_, g_as);
    cudaGetSymbolAddress((void**)&ad_, g_ad);
    cudaGetSymbolAddress((void**)&wbuf, g_w);
    cudaGetSymbolAddress((void**)&counts, g_counts);
    cudaGetSymbolAddress((void**)&off, g_off);
    cudaGetSymbolAddress((void**)&cursor, g_cursor);
    cudaGetSymbolAddress((void**)&bsum, g_bsum);
    cudaGetSymbolAddress((void**)&csr, g_csr);
    cudaGetSymbolAddress((void**)&bsw, g_bsplit);

    cudaFuncSetAttribute(gemm_tc_kernel, cudaFuncAttributeMaxDynamicSharedMemorySize, GEMM_SMEM);

    const size_t TOPO = 655360, OW1 = 262144, OW2 = 393216, OAW = 524288, OFUS = 2621440;
    const size_t NH = (size_t)NN * HIDD;
    dim3 ggridK5(2, cdiv(NN, 128), KK + 1);
    dim3 ggridK(2, cdiv(NN, 128), KK);
    dim3 egridK(cdiv(EDGES, 256), KK);
    dim3 sgridK(SCAN_BLOCKS, KK);
    dim3 ngridK(NN / 4, KK);
    dim3 agridK(NN, KK);

    // startup
    bsplit_all_kernel<<<dim3(512, 17), 256>>>(gW0, gW1, gW2, aW, fW1, bsw);
    zero_int_kernel<<<cdiv(KK * NN, 256), 256>>>(counts, KK * NN);
    split_act_kernel<<<cdiv(NN * IN_DIM, 256), 256>>>(x, xs_hi, xs_lo, NN, IN_DIM, IN_DIM, 0);
    split_act_kernel<<<cdiv(NN * HIDD, 256), 256>>>(style, st_hi, st_lo, NN, HIDD, IN_DIM, 0);
    split_act_kernel<<<cdiv(NN * HIDD, 256), 256>>>(stress, st_hi, st_lo, NN, HIDD, IN_DIM, HIDD);

    // GCN L0 GEMMs (z<4) + fusion GEMM (z==4)
    gemm_tc_kernel<<<ggridK5, 256, GEMM_SMEM>>>(xs_hi, xs_lo, 0, IN_DIM,
                                                bsw, TOPO, h1, NH, NN, IN_DIM, KK,
                                                st_hi, st_lo, bsw + OFUS, hf,
                                                nullptr, nullptr, nullptr, nullptr);

    // CSR build
    hist_kernel<<<egridK, 256>>>(ei[0], ei[1], ei[2], ei[3], counts);
    scanA_kernel<<<sgridK, 1024>>>(counts, off, bsum);
    scanC_kernel<<<sgridK, 1024>>>(counts, off, cursor, bsum, dinv);
    fillcsr_kernel<<<egridK, 256>>>(ei[0], ei[1], ei[2], ei[3], cursor, csr);

    gcn_gather_kernel<<<ngridK, 256>>>(h1, csr, off, dinv, gb0, hs_hi, hs_lo);

    gemm_tc_kernel<<<ggridK, 256, GEMM_SMEM>>>(hs_hi, hs_lo, NH, HIDD,
                                               bsw + OW1, TOPO, h1, NH, NN, HIDD, -1,
                                               nullptr, nullptr, nullptr, nullptr,
                                               nullptr, nullptr, nullptr, nullptr);
    gcn_gather_kernel<<<ngridK, 256>>>(h1, csr, off, dinv, gb1, hs_hi, hs_lo);

    gemm_tc_kernel<<<ggridK, 256, GEMM_SMEM>>>(hs_hi, hs_lo, NH, HIDD,
                                               bsw + OW2, TOPO, h1, NH, NN, HIDD, -1,
                                               nullptr, nullptr, nullptr, nullptr,
                                               nullptr, nullptr, nullptr, nullptr);
    gcn_gather_kernel<<<ngridK, 256>>>(h1, csr, off, dinv, gb2, hs_hi, hs_lo);

    // GAT GEMM with fused per-node head scores
    gemm_tc_kernel<<<ggridK, 256, GEMM_SMEM>>>(hs_hi, hs_lo, NH, HIDD,
                                               bsw + OAW, TOPO, h1, NH, NN, HIDD, -1,
                                               nullptr, nullptr, nullptr, nullptr,
                                               aas, aad, as_, ad_);
    gat_gather_ln_kernel<<<agridK, 256>>>(h1, csr, off, as_, ad_, ab, lg, lb, outs);

    // fusion tail
    fuse_logits_kernel<<<cdiv(NN * 32, 256), 256>>>(hf, fb1, fW2, fb2, wbuf);
    combine_kernel<<<NN, 256>>>(wbuf, (float*)d_out);
}

// round 17
// speedup vs baseline: 1.2412x; 1.0343x over previous
#include <cuda_runtime.h>
#include <cuda_bf16.h>
#include <math.h>
#include <stdint.h>

#define NN 50000
#define IN_DIM 512
#define HIDD 256
#define HEADS 8
#define HC 32
#define EDGES 600000
#define KK 4
#define LN_EPS 1e-5f
#define SCAN_BLOCKS 49

// ---------------- scratch (per-topology) ----------------
__device__ float g_h1[KK * NN * HIDD];
__device__ float g_hf[NN * HIDD];
__device__ __nv_bfloat16 g_hs_hi[KK * NN * HIDD];
__device__ __nv_bfloat16 g_hs_lo[KK * NN * HIDD];
__device__ __nv_bfloat16 g_xs_hi[NN * IN_DIM];
__device__ __nv_bfloat16 g_xs_lo[NN * IN_DIM];
__device__ __nv_bfloat16 g_st_hi[NN * IN_DIM];
__device__ __nv_bfloat16 g_st_lo[NN * IN_DIM];
__device__ float g_outs[KK * NN * HIDD];
__device__ float g_dinv[KK * NN];
__device__ float g_as[KK * NN * HEADS];
__device__ float g_ad[KK * NN * HEADS];
__device__ float g_w[NN * KK];
__device__ int g_counts[KK * NN];
__device__ int g_off[KK * (NN + 1)];
__device__ int g_cursor[KK * NN];
__device__ int g_bsum[KK * SCAN_BLOCKS];
__device__ int g_csr[KK * EDGES];
__device__ __nv_bfloat16 g_bsplit[88 * 32768];

__device__ __forceinline__ float lrelu(float x) { return x > 0.f ? x : 0.2f * x; }
static inline int cdiv(int a, int b) { return (a + b - 1) / b; }

__device__ __forceinline__ uint32_t pk_bf16x2(__nv_bfloat16 a, __nv_bfloat16 b) {
    return (uint32_t)__bfloat16_as_ushort(a) | ((uint32_t)__bfloat16_as_ushort(b) << 16);
}

__device__ __forceinline__ void mma16816(float* c, const uint32_t* a, const uint32_t* b) {
    asm volatile(
        "mma.sync.aligned.m16n8k16.row.col.f32.bf16.bf16.f32 "
        "{%0,%1,%2,%3}, {%4,%5,%6,%7}, {%8,%9}, {%0,%1,%2,%3};"
        : "+f"(c[0]), "+f"(c[1]), "+f"(c[2]), "+f"(c[3])
        : "r"(a[0]), "r"(a[1]), "r"(a[2]), "r"(a[3]), "r"(b[0]), "r"(b[1]));
}

#define LDSM4(r, addr) \
    asm volatile("ldmatrix.sync.aligned.m8n8.x4.shared.b16 {%0,%1,%2,%3}, [%4];" \
                 : "=r"((r)[0]), "=r"((r)[1]), "=r"((r)[2]), "=r"((r)[3]) : "r"(addr))

__device__ __forceinline__ void cp16(uint32_t saddr, const void* gptr, bool pred) {
    int sz = pred ? 16 : 0;
    asm volatile("cp.async.cg.shared.global [%0], [%1], 16, %2;"
                 :: "r"(saddr), "l"(gptr), "r"(sz) : "memory");
}

// ---------------- weight split (all matrices, one launch) ----------------
__global__ void bsplit_all_kernel(const float* __restrict__ gW0, const float* __restrict__ gW1,
                                  const float* __restrict__ gW2, const float* __restrict__ aW,
                                  const float* __restrict__ fW1, __nv_bfloat16* __restrict__ bsw) {
    int seg = blockIdx.y;
    const float* src;
    __nv_bfloat16* dst;
    int total;
    if (seg == 16) {
        src = fW1; dst = bsw + 2621440; total = 512 * 256;
    } else {
        int topo = seg >> 2, which = seg & 3;
        __nv_bfloat16* tb = bsw + (size_t)topo * 655360;
        if (which == 0)      { src = gW0 + (size_t)topo * 512 * 256; dst = tb;          total = 512 * 256; }
        else if (which == 1) { src = gW1 + (size_t)topo * 256 * 256; dst = tb + 262144; total = 256 * 256; }
        else if (which == 2) { src = gW2 + (size_t)topo * 256 * 256; dst = tb + 393216; total = 256 * 256; }
        else                 { src = aW  + (size_t)topo * 256 * 256; dst = tb + 524288; total = 256 * 256; }
    }
    int idx = blockIdx.x * 256 + threadIdx.x;
    if (idx >= total) return;
    int kk = idx >> 8;
    int n = idx & 255;
    float w = src[idx];
    __nv_bfloat16 hi = __float2bfloat16_rn(w);
    __nv_bfloat16 lo = __float2bfloat16_rn(w - __bfloat162float(hi));
    int chunk = kk >> 5, kin = kk & 31;
    __nv_bfloat16* base = dst + (size_t)chunk * 16384;
    base[n * 32 + kin] = hi;
    base[n * 32 + kin + 8192] = lo;
}

// ---------------- activation split: x / style / stress in one launch, x4 vectorized ----------------
// seg 0: x[NN,512] -> xs (ld 512, off 0)
// seg 1: style[NN,256] -> st (ld 512, off 0)
// seg 2: stress[NN,256] -> st (ld 512, off 256)
__global__ void split_all_acts_kernel(const float* __restrict__ x, const float* __restrict__ style,
                                      const float* __restrict__ stress,
                                      __nv_bfloat16* __restrict__ xhi, __nv_bfloat16* __restrict__ xlo,
                                      __nv_bfloat16* __restrict__ sthi, __nv_bfloat16* __restrict__ stlo) {
    int seg = blockIdx.y;
    const float* src;
    __nv_bfloat16 *dhi, *dlo;
    int cols, dst_off, total;
    if (seg == 0)      { src = x;      dhi = xhi;  dlo = xlo;  cols = 512; dst_off = 0;   total = NN * 512; }
    else if (seg == 1) { src = style;  dhi = sthi; dlo = stlo; cols = 256; dst_off = 0;   total = NN * 256; }
    else               { src = stress; dhi = sthi; dlo = stlo; cols = 256; dst_off = 256; total = NN * 256; }
    int e4 = blockIdx.x * 256 + threadIdx.x;     // index of 4-elem group
    int idx = e4 * 4;
    if (idx >= total) return;
    float4 v = *(const float4*)(src + idx);
    __nv_bfloat16 h0 = __float2bfloat16_rn(v.x);
    __nv_bfloat16 h1 = __float2bfloat16_rn(v.y);
    __nv_bfloat16 h2 = __float2bfloat16_rn(v.z);
    __nv_bfloat16 h3 = __float2bfloat16_rn(v.w);
    __nv_bfloat16 l0 = __float2bfloat16_rn(v.x - __bfloat162float(h0));
    __nv_bfloat16 l1 = __float2bfloat16_rn(v.y - __bfloat162float(h1));
    __nv_bfloat16 l2 = __float2bfloat16_rn(v.z - __bfloat162float(h2));
    __nv_bfloat16 l3 = __float2bfloat16_rn(v.w - __bfloat162float(h3));
    int r = idx / cols, c = idx - r * cols;      // c is 4-aligned
    size_t o = (size_t)r * 512 + dst_off + c;
    *(uint2*)(dhi + o) = make_uint2(pk_bf16x2(h0, h1), pk_bf16x2(h2, h3));
    *(uint2*)(dlo + o) = make_uint2(pk_bf16x2(l0, l1), pk_bf16x2(l2, l3));
}

// ---------------- CSR build (batched over topology via blockIdx.y) ----------------
__global__ void zero_int_kernel(int* p, int n) {
    int i = blockIdx.x * 256 + threadIdx.x;
    if (i < n) p[i] = 0;
}

__global__ void hist_kernel(const int* __restrict__ e0, const int* __restrict__ e1,
                            const int* __restrict__ e2, const int* __restrict__ e3,
                            int* __restrict__ counts) {
    int k = blockIdx.y;
    const int* dst = (k == 0 ? e0 : k == 1 ? e1 : k == 2 ? e2 : e3) + EDGES;
    int i = blockIdx.x * 256 + threadIdx.x;
    if (i < EDGES) atomicAdd(&counts[k * NN + dst[i]], 1);
}

// per-block inclusive scan via warp shuffles (2 barriers)
__global__ void scanA_kernel(const int* __restrict__ counts, int* __restrict__ scanbuf,
                             int* __restrict__ bsum) {
    int k = blockIdx.y;
    counts += (size_t)k * NN;
    scanbuf += (size_t)k * (NN + 1);
    bsum += (size_t)k * SCAN_BLOCKS;
    __shared__ int ws[32];
    int b = blockIdx.x, t = threadIdx.x;
    int lane = t & 31, w = t >> 5;
    int i = b * 1024 + t;
    int v = (i < NN) ? counts[i] : 0;
    int xv = v;
#pragma unroll
    for (int o = 1; o < 32; o <<= 1) {
        int y = __shfl_up_sync(0xffffffffu, xv, o);
        if (lane >= o) xv += y;
    }
    if (lane == 31) ws[w] = xv;
    __syncthreads();
    if (w == 0) {
        int s = ws[lane];
#pragma unroll
        for (int o = 1; o < 32; o <<= 1) {
            int y = __shfl_up_sync(0xffffffffu, s, o);
            if (lane >= o) s += y;
        }
        ws[lane] = s;
    }
    __syncthreads();
    int incl = xv + (w ? ws[w - 1] : 0);
    if (i < NN) scanbuf[i] = incl;
    if (t == 1023) bsum[b] = incl;
}

__global__ void scanC_kernel(const int* __restrict__ counts, int* __restrict__ off,
                             int* __restrict__ cursor, const int* __restrict__ bsum,
                             float* __restrict__ dinv) {
    int k = blockIdx.y;
    counts += (size_t)k * NN;
    off += (size_t)k * (NN + 1);
    cursor += (size_t)k * NN;
    bsum += (size_t)k * SCAN_BLOCKS;
    dinv += (size_t)k * NN;
    int b = blockIdx.x, t = threadIdx.x;
    int i = b * 1024 + t;
    if (i >= NN) return;
    int prefix = 0;
    for (int j = 0; j < b; j++) prefix += bsum[j];
    int cnt = counts[i];
    int excl = off[i] - cnt + prefix;
    off[i] = excl;
    cursor[i] = excl;
    dinv[i] = rsqrtf((float)cnt + 1.0f);
    if (i == NN - 1) off[NN] = excl + cnt;
}

__global__ void fillcsr_kernel(const int* __restrict__ e0, const int* __restrict__ e1,
                               const int* __restrict__ e2, const int* __restrict__ e3,
                               int* __restrict__ cursor, int* __restrict__ csr) {
    int k = blockIdx.y;
    const int* ep = (k == 0 ? e0 : k == 1 ? e1 : k == 2 ? e2 : e3);
    const int* src = ep;
    const int* dst = ep + EDGES;
    cursor += (size_t)k * NN;
    csr += (size_t)k * EDGES;
    int i = blockIdx.x * 256 + threadIdx.x;
    if (i >= EDGES) return;
    int pos = atomicAdd(&cursor[dst[i]], 1);
    csr[pos] = src[i];
}

// ---------------- tensor-core GEMM, batched over blockIdx.z; single barrier per chunk ----------------
#define SA 40
#define STAGE_BYTES 40960
#define GEMM_SMEM (2 * STAGE_BYTES)

__global__ void __launch_bounds__(256, 2)
gemm_tc_kernel(const __nv_bfloat16* __restrict__ Ahi, const __nv_bfloat16* __restrict__ Alo,
               size_t strideA, int lda,
               const __nv_bfloat16* __restrict__ Bsw, size_t strideB,
               float* __restrict__ C, size_t strideC, int M, int Kd, int zAlt,
               const __nv_bfloat16* __restrict__ A2hi, const __nv_bfloat16* __restrict__ A2lo,
               const __nv_bfloat16* __restrict__ B2, float* __restrict__ C2,
               const float* __restrict__ asrc, const float* __restrict__ adst,
               float* __restrict__ as_out, float* __restrict__ ad_out) {
    extern __shared__ char smem[];
    const uint32_t sbase = (uint32_t)__cvta_generic_to_shared(smem);

    const int z = blockIdx.z;
    if (z == zAlt) {
        Ahi = A2hi; Alo = A2lo; Bsw = B2; C = C2;
    } else {
        Ahi += (size_t)z * strideA;
        Alo += (size_t)z * strideA;
        Bsw += (size_t)z * strideB;
        C += (size_t)z * strideC;
    }
    if (asrc) {
        asrc += (size_t)z * HEADS * HC;
        adst += (size_t)z * HEADS * HC;
        as_out += (size_t)z * NN * HEADS;
        ad_out += (size_t)z * NN * HEADS;
    }

    const int tid = threadIdx.x;
    const int wid = tid >> 5;
    const int lane = tid & 31;
    const int g = lane >> 2;
    const int tig = lane & 3;

    const int rowBase = blockIdx.y * 128;
    const int colBase = blockIdx.x * 128;
    const int warp_m = (wid >> 2) * 64;
    const int warp_n = (wid & 3) * 32;

    const int srow = tid >> 1;
    const int shalf = tid & 1;
    const int rg = rowBase + srow;
    const bool rok = (rg < M);

    float acc[4][4][4];
#pragma unroll
    for (int i = 0; i < 4; i++)
#pragma unroll
        for (int j = 0; j < 4; j++)
#pragma unroll
            for (int q = 0; q < 4; q++) acc[i][j][q] = 0.f;

    const uint32_t soff = (srow * SA + shalf * 16) * 2;
    const uint32_t a_loff = (uint32_t)(warp_m + (lane & 15)) * (SA * 2) + ((lane & 16) ? 16 : 0);
    const uint32_t b_loff = (uint32_t)(warp_n + (lane & 7) + ((lane & 16) ? 8 : 0)) * (SA * 2)
                          + ((lane & 8) ? 16 : 0);

    auto stage_load = [&](int c, int s) {
        uint32_t st = sbase + s * STAGE_BYTES;
        size_t go = (size_t)rg * lda + (c << 5) + shalf * 16;
        cp16(st + soff,              Ahi + go,     rok);
        cp16(st + soff + 16,         Ahi + go + 8, rok);
        cp16(st + 10240 + soff,      Alo + go,     rok);
        cp16(st + 10240 + soff + 16, Alo + go + 8, rok);
        const __nv_bfloat16* Bc = Bsw + (size_t)c * 16384 + (size_t)(colBase + srow) * 32 + shalf * 16;
        cp16(st + 20480 + soff,      Bc,        true);
        cp16(st + 20480 + soff + 16, Bc + 8,    true);
        cp16(st + 30720 + soff,      Bc + 8192, true);
        cp16(st + 30720 + soff + 16, Bc + 8200, true);
    };

    const int nChunks = Kd >> 5;
    stage_load(0, 0);
    asm volatile("cp.async.commit_group;" ::: "memory");

    for (int c = 0; c < nChunks; c++) {
        asm volatile("cp.async.wait_group 0;" ::: "memory");
        __syncthreads();
        if (c + 1 < nChunks) {
            stage_load(c + 1, (c + 1) & 1);
            asm volatile("cp.async.commit_group;" ::: "memory");
        }

        const uint32_t st = sbase + (c & 1) * STAGE_BYTES;

#pragma unroll
        for (int ks = 0; ks < 2; ks++) {
            const uint32_t kb = ks * 32;
            uint32_t ah[4][4], al[4][4];
#pragma unroll
            for (int mt = 0; mt < 4; mt++) {
                uint32_t ad = st + a_loff + mt * (16 * SA * 2) + kb;
                LDSM4(ah[mt], ad);
                LDSM4(al[mt], ad + 10240);
            }
            uint32_t bh[4][2], bl[4][2];
#pragma unroll
            for (int p = 0; p < 2; p++) {
                uint32_t bd = st + 20480 + b_loff + p * (16 * SA * 2) + kb;
                uint32_t t4[4];
                LDSM4(t4, bd);
                bh[2 * p][0] = t4[0]; bh[2 * p][1] = t4[1];
                bh[2 * p + 1][0] = t4[2]; bh[2 * p + 1][1] = t4[3];
                LDSM4(t4, bd + 10240);
                bl[2 * p][0] = t4[0]; bl[2 * p][1] = t4[1];
                bl[2 * p + 1][0] = t4[2]; bl[2 * p + 1][1] = t4[3];
            }
#pragma unroll
            for (int mt = 0; mt < 4; mt++)
#pragma unroll
                for (int nt = 0; nt < 4; nt++) {
                    mma16816(acc[mt][nt], ah[mt], bh[nt]);
                    mma16816(acc[mt][nt], ah[mt], bl[nt]);
                    mma16816(acc[mt][nt], al[mt], bh[nt]);
                }
        }
    }

#pragma unroll
    for (int mt = 0; mt < 4; mt++) {
        int row0 = rowBase + warp_m + mt * 16 + g;
        int row1 = row0 + 8;
#pragma unroll
        for (int nt = 0; nt < 4; nt++) {
            int col = colBase + warp_n + nt * 8 + tig * 2;
            if (row0 < M)
                *(float2*)(C + (size_t)row0 * 256 + col) = make_float2(acc[mt][nt][0], acc[mt][nt][1]);
            if (row1 < M)
                *(float2*)(C + (size_t)row1 * 256 + col) = make_float2(acc[mt][nt][2], acc[mt][nt][3]);
        }
    }

    if (asrc) {
        const int head = (colBase + warp_n) >> 5;
#pragma unroll
        for (int mt = 0; mt < 4; mt++) {
            float s0 = 0.f, d0 = 0.f, s1 = 0.f, d1 = 0.f;
#pragma unroll
            for (int nt = 0; nt < 4; nt++) {
                int lc = nt * 8 + tig * 2;
                float a0 = asrc[head * HC + lc], a1 = asrc[head * HC + lc + 1];
                float b0 = adst[head * HC + lc], b1 = adst[head * HC + lc + 1];
                s0 += acc[mt][nt][0] * a0 + acc[mt][nt][1] * a1;
                d0 += acc[mt][nt][0] * b0 + acc[mt][nt][1] * b1;
                s1 += acc[mt][nt][2] * a0 + acc[mt][nt][3] * a1;
                d1 += acc[mt][nt][2] * b0 + acc[mt][nt][3] * b1;
            }
            s0 += __shfl_xor_sync(0xffffffffu, s0, 1); s0 += __shfl_xor_sync(0xffffffffu, s0, 2);
            d0 += __shfl_xor_sync(0xffffffffu, d0, 1); d0 += __shfl_xor_sync(0xffffffffu, d0, 2);
            s1 += __shfl_xor_sync(0xffffffffu, s1, 1); s1 += __shfl_xor_sync(0xffffffffu, s1, 2);
            d1 += __shfl_xor_sync(0xffffffffu, d1, 1); d1 += __shfl_xor_sync(0xffffffffu, d1, 2);
            int row0 = rowBase + warp_m + mt * 16 + g;
            int row1 = row0 + 8;
            if (tig == 0) {
                if (row0 < M) { as_out[row0 * HEADS + head] = s0; ad_out[row0 * HEADS + head] = d0; }
                if (row1 < M) { as_out[row1 * HEADS + head] = s1; ad_out[row1 * HEADS + head] = d1; }
            }
        }
    }
}

// ---------------- GCN gather (batched over blockIdx.y; edge loop unrolled x4) ----------------
__global__ void gcn_gather_kernel(const float* __restrict__ h, const int* __restrict__ csr,
                                  const int* __restrict__ off, const float* __restrict__ dinv,
                                  const float* __restrict__ bias,
                                  __nv_bfloat16* __restrict__ ohi, __nv_bfloat16* __restrict__ olo) {
    const int k = blockIdx.y;
    const size_t NH = (size_t)NN * HIDD;
    h += (size_t)k * NH;
    csr += (size_t)k * EDGES;
    off += (size_t)k * (NN + 1);
    dinv += (size_t)k * NN;
    bias += (size_t)k * HIDD;
    ohi += (size_t)k * NH;
    olo += (size_t)k * NH;

    int tid = threadIdx.x;
    int n = blockIdx.x * 4 + (tid >> 6);
    int t = tid & 63;
    size_t base = (size_t)n * HIDD + t * 4;
    float dn = dinv[n];
    float dn2 = dn * dn;
    float4 hv = *(const float4*)(h + base);
    float4 bv = *(const float4*)(bias + t * 4);
    float4 acc = make_float4(hv.x * dn2 + bv.x, hv.y * dn2 + bv.y,
                             hv.z * dn2 + bv.z, hv.w * dn2 + bv.w);
    int beg = __ldg(&off[n]), end = __ldg(&off[n + 1]);
    int j = beg;
    for (; j + 4 <= end; j += 4) {
        int s0 = __ldg(&csr[j + 0]);
        int s1 = __ldg(&csr[j + 1]);
        int s2 = __ldg(&csr[j + 2]);
        int s3 = __ldg(&csr[j + 3]);
        float c0 = __ldg(&dinv[s0]) * dn;
        float c1 = __ldg(&dinv[s1]) * dn;
        float c2 = __ldg(&dinv[s2]) * dn;
        float c3 = __ldg(&dinv[s3]) * dn;
        float4 v0 = *(const float4*)(h + (size_t)s0 * HIDD + t * 4);
        float4 v1 = *(const float4*)(h + (size_t)s1 * HIDD + t * 4);
        float4 v2 = *(const float4*)(h + (size_t)s2 * HIDD + t * 4);
        float4 v3 = *(const float4*)(h + (size_t)s3 * HIDD + t * 4);
        acc.x += v0.x * c0; acc.y += v0.y * c0; acc.z += v0.z * c0; acc.w += v0.w * c0;
        acc.x += v1.x * c1; acc.y += v1.y * c1; acc.z += v1.z * c1; acc.w += v1.w * c1;
        acc.x += v2.x * c2; acc.y += v2.y * c2; acc.z += v2.z * c2; acc.w += v2.w * c2;
        acc.x += v3.x * c3; acc.y += v3.y * c3; acc.z += v3.z * c3; acc.w += v3.w * c3;
    }
    for (; j < end; j++) {
        int s = __ldg(&csr[j]);
        float cf = __ldg(&dinv[s]) * dn;
        float4 v = *(const float4*)(h + (size_t)s * HIDD + t * 4);
        acc.x += v.x * cf; acc.y += v.y * cf; acc.z += v.z * cf; acc.w += v.w * cf;
    }
    acc.x = fmaxf(acc.x, 0.f); acc.y = fmaxf(acc.y, 0.f);
    acc.z = fmaxf(acc.z, 0.f); acc.w = fmaxf(acc.w, 0.f);
    __nv_bfloat16 h0 = __float2bfloat16_rn(acc.x);
    __nv_bfloat16 h1b = __float2bfloat16_rn(acc.y);
    __nv_bfloat16 h2 = __float2bfloat16_rn(acc.z);
    __nv_bfloat16 h3 = __float2bfloat16_rn(acc.w);
    __nv_bfloat16 l0 = __float2bfloat16_rn(acc.x - __bfloat162float(h0));
    __nv_bfloat16 l1 = __float2bfloat16_rn(acc.y - __bfloat162float(h1b));
    __nv_bfloat16 l2 = __float2bfloat16_rn(acc.z - __bfloat162float(h2));
    __nv_bfloat16 l3 = __float2bfloat16_rn(acc.w - __bfloat162float(h3));
    *(uint2*)(ohi + base) = make_uint2(pk_bf16x2(h0, h1b), pk_bf16x2(h2, h3));
    *(uint2*)(olo + base) = make_uint2(pk_bf16x2(l0, l1), pk_bf16x2(l2, l3));
}

// ---------------- GAT gather + one-pass softmax (self-score reference) + LN ----------------
__global__ void gat_gather_ln_kernel(const float* __restrict__ hg, const int* __restrict__ csr,
                                     const int* __restrict__ off, const float* __restrict__ as_,
                                     const float* __restrict__ ad_, const float* __restrict__ ab,
                                     const float* __restrict__ lg, const float* __restrict__ lb,
                                     float* __restrict__ outp) {
    const int k = blockIdx.y;
    const size_t NH = (size_t)NN * HIDD;
    hg += (size_t)k * NH;
    csr += (size_t)k * EDGES;
    off += (size_t)k * (NN + 1);
    as_ += (size_t)k * NN * HEADS;
    ad_ += (size_t)k * NN * HEADS;
    ab += (size_t)k * HIDD;
    lg += (size_t)k * HIDD;
    lb += (size_t)k * HIDD;
    outp += (size_t)k * NH;

    int n = blockIdx.x, c = threadIdx.x, h = c >> 5;
    int beg = __ldg(&off[n]), end = __ldg(&off[n + 1]);
    float adn = __ldg(&ad_[n * HEADS + h]);
    float m = lrelu(__ldg(&as_[n * HEADS + h]) + adn);

    float denom = 1.0f;
    float acc = hg[(size_t)n * HIDD + c];
    {
        int j = beg;
        for (; j + 4 <= end; j += 4) {
            int s0 = __ldg(&csr[j + 0]);
            int s1 = __ldg(&csr[j + 1]);
            int s2 = __ldg(&csr[j + 2]);
            int s3 = __ldg(&csr[j + 3]);
            float w0 = expf(lrelu(__ldg(&as_[s0 * HEADS + h]) + adn) - m);
            float w1 = expf(lrelu(__ldg(&as_[s1 * HEADS + h]) + adn) - m);
            float w2 = expf(lrelu(__ldg(&as_[s2 * HEADS + h]) + adn) - m);
            float w3 = expf(lrelu(__ldg(&as_[s3 * HEADS + h]) + adn) - m);
            float g0 = hg[(size_t)s0 * HIDD + c];
            float g1 = hg[(size_t)s1 * HIDD + c];
            float g2 = hg[(size_t)s2 * HIDD + c];
            float g3 = hg[(size_t)s3 * HIDD + c];
            denom += w0; acc += g0 * w0;
            denom += w1; acc += g1 * w1;
            denom += w2; acc += g2 * w2;
            denom += w3; acc += g3 * w3;
        }
        for (; j < end; j++) {
            int s = __ldg(&csr[j]);
            float w = expf(lrelu(__ldg(&as_[s * HEADS + h]) + adn) - m);
            denom += w;
            acc += hg[(size_t)s * HIDD + c] * w;
        }
    }
    float val = acc / denom + ab[c];

    __shared__ float red[8];
    __shared__ float s_mu, s_rstd;
    float s = val;
#pragma unroll
    for (int o = 16; o; o >>= 1) s += __shfl_down_sync(0xffffffffu, s, o);
    if ((c & 31) == 0) red[c >> 5] = s;
    __syncthreads();
    if (c == 0) {
        float t = 0.f;
#pragma unroll
        for (int i = 0; i < 8; i++) t += red[i];
        s_mu = t * (1.0f / HIDD);
    }
    __syncthreads();
    float dv = val - s_mu;
    float q = dv * dv;
#pragma unroll
    for (int o = 16; o; o >>= 1) q += __shfl_down_sync(0xffffffffu, q, o);
    if ((c & 31) == 0) red[c >> 5] = q;
    __syncthreads();
    if (c == 0) {
        float t = 0.f;
#pragma unroll
        for (int i = 0; i < 8; i++) t += red[i];
        s_rstd = rsqrtf(t * (1.0f / HIDD) + LN_EPS);
    }
    __syncthreads();
    outp[(size_t)n * HIDD + c] = dv * s_rstd * lg[c] + lb[c];
}

// ---------------- fusion tail ----------------
__global__ void fuse_logits_kernel(const float* __restrict__ t, const float* __restrict__ b1,
                                   const float* __restrict__ W2, const float* __restrict__ b2,
                                   float* __restrict__ w) {
    int gw = (blockIdx.x * blockDim.x + threadIdx.x) >> 5;
    int lane = threadIdx.x & 31;
    if (gw >= NN) return;
    const float* row = t + (size_t)gw * HIDD;
    float a0 = 0.f, a1 = 0.f, a2 = 0.f, a3 = 0.f;
    for (int c = lane; c < HIDD; c += 32) {
        float tv = tanhf(row[c] + b1[c]);
        a0 += tv * W2[c * 4 + 0];
        a1 += tv * W2[c * 4 + 1];
        a2 += tv * W2[c * 4 + 2];
        a3 += tv * W2[c * 4 + 3];
    }
#pragma unroll
    for (int o = 16; o; o >>= 1) {
        a0 += __shfl_down_sync(0xffffffffu, a0, o);
        a1 += __shfl_down_sync(0xffffffffu, a1, o);
        a2 += __shfl_down_sync(0xffffffffu, a2, o);
        a3 += __shfl_down_sync(0xffffffffu, a3, o);
    }
    if (lane == 0) {
        float l0 = a0 + b2[0], l1 = a1 + b2[1], l2 = a2 + b2[2], l3 = a3 + b2[3];
        float mx = fmaxf(fmaxf(l0, l1), fmaxf(l2, l3));
        float e0 = expf(l0 - mx), e1 = expf(l1 - mx), e2 = expf(l2 - mx), e3 = expf(l3 - mx);
        float inv = 1.0f / (e0 + e1 + e2 + e3);
        w[gw * 4 + 0] = e0 * inv;
        w[gw * 4 + 1] = e1 * inv;
        w[gw * 4 + 2] = e2 * inv;
        w[gw * 4 + 3] = e3 * inv;
    }
}

__global__ void combine_kernel(const float* __restrict__ w, float* __restrict__ out) {
    int idx = blockIdx.x * 256 + threadIdx.x;
    int n = idx >> 8;
    float acc = 0.f;
#pragma unroll
    for (int k = 0; k < KK; k++) acc += w[n * KK + k] * g_outs[(size_t)k * NN * HIDD + idx];
    out[idx] = acc;
}

// ---------------- host ----------------
extern "C" void kernel_launch(void* const* d_in, const int* in_sizes, int n_in,
                              void* d_out, int out_size) {
    const float *x, *style, *stress;
    const int* ei[KK];
    int base;
    if (in_sizes[1] == 2 * EDGES) {
        x = (const float*)d_in[0];
        for (int k = 0; k < KK; k++) ei[k] = (const int*)d_in[1 + k];
        style = (const float*)d_in[5];
        stress = (const float*)d_in[6];
        base = 7;
    } else {
        x = (const float*)d_in[0];
        style = (const float*)d_in[1];
        stress = (const float*)d_in[2];
        for (int k = 0; k < KK; k++) ei[k] = (const int*)d_in[3 + k];
        base = 7;
    }
    const float* gW0 = (const float*)d_in[base + 0];
    const float* gb0 = (const float*)d_in[base + 1];
    const float* gW1 = (const float*)d_in[base + 2];
    const float* gb1 = (const float*)d_in[base + 3];
    const float* gW2 = (const float*)d_in[base + 4];
    const float* gb2 = (const float*)d_in[base + 5];
    const float* aW  = (const float*)d_in[base + 6];
    const float* aas = (const float*)d_in[base + 7];
    const float* aad = (const float*)d_in[base + 8];
    const float* ab  = (const float*)d_in[base + 9];
    const float* lg  = (const float*)d_in[base + 10];
    const float* lb  = (const float*)d_in[base + 11];
    const float* fW1 = (const float*)d_in[base + 12];
    const float* fb1 = (const float*)d_in[base + 13];
    const float* fW2 = (const float*)d_in[base + 14];
    const float* fb2 = (const float*)d_in[base + 15];

    float *h1, *hf, *outs, *dinv, *as_, *ad_, *wbuf;
    __nv_bfloat16 *hs_hi, *hs_lo, *xs_hi, *xs_lo, *st_hi, *st_lo, *bsw;
    int *counts, *off, *cursor, *bsum, *csr;
    cudaGetSymbolAddress((void**)&h1, g_h1);
    cudaGetSymbolAddress((void**)&hf, g_hf);
    cudaGetSymbolAddress((void**)&hs_hi, g_hs_hi);
    cudaGetSymbolAddress((void**)&hs_lo, g_hs_lo);
    cudaGetSymbolAddress((void**)&xs_hi, g_xs_hi);
    cudaGetSymbolAddress((void**)&xs_lo, g_xs_lo);
    cudaGetSymbolAddress((void**)&st_hi, g_st_hi);
    cudaGetSymbolAddress((void**)&st_lo, g_st_lo);
    cudaGetSymbolAddress((void**)&outs, g_outs);
    cudaGetSymbolAddress((void**)&dinv, g_dinv);
    cudaGetSymbolAddress((void**)&as_, g_as);
    cudaGetSymbolAddress((void**)&ad_, g_ad);
    cudaGetSymbolAddress((void**)&wbuf, g_w);
    cudaGetSymbolAddress((void**)&counts, g_counts);
    cudaGetSymbolAddress((void**)&off, g_off);
    cudaGetSymbolAddress((void**)&cursor, g_cursor);
    cudaGetSymbolAddress((void**)&bsum, g_bsum);
    cudaGetSymbolAddress((void**)&csr, g_csr);
    cudaGetSymbolAddress((void**)&bsw, g_bsplit);

    cudaFuncSetAttribute(gemm_tc_kernel, cudaFuncAttributeMaxDynamicSharedMemorySize, GEMM_SMEM);

    const size_t TOPO = 655360, OW1 = 262144, OW2 = 393216, OAW = 524288, OFUS = 2621440;
    const size_t NH = (size_t)NN * HIDD;
    dim3 ggridK5(2, cdiv(NN, 128), KK + 1);
    dim3 ggridK(2, cdiv(NN, 128), KK);
    dim3 egridK(cdiv(EDGES, 256), KK);
    dim3 sgridK(SCAN_BLOCKS, KK);
    dim3 ngridK(NN / 4, KK);
    dim3 agridK(NN, KK);

    // startup: launches #1..#3; #4 = batched K=512 GEMM (gets profiled by ncu -s 5)
    bsplit_all_kernel<<<dim3(512, 17), 256>>>(gW0, gW1, gW2, aW, fW1, bsw);
    zero_int_kernel<<<cdiv(KK * NN, 256), 256>>>(counts, KK * NN);
    split_all_acts_kernel<<<dim3(cdiv(NN * IN_DIM / 4, 256), 3), 256>>>(x, style, stress,
                                                                        xs_hi, xs_lo, st_hi, st_lo);

    gemm_tc_kernel<<<ggridK5, 256, GEMM_SMEM>>>(xs_hi, xs_lo, 0, IN_DIM,
                                                bsw, TOPO, h1, NH, NN, IN_DIM, KK,
                                                st_hi, st_lo, bsw + OFUS, hf,
                                                nullptr, nullptr, nullptr, nullptr);

    // CSR build
    hist_kernel<<<egridK, 256>>>(ei[0], ei[1], ei[2], ei[3], counts);
    scanA_kernel<<<sgridK, 1024>>>(counts, off, bsum);
    scanC_kernel<<<sgridK, 1024>>>(counts, off, cursor, bsum, dinv);
    fillcsr_kernel<<<egridK, 256>>>(ei[0], ei[1], ei[2], ei[3], cursor, csr);

    gcn_gather_kernel<<<ngridK, 256>>>(h1, csr, off, dinv, gb0, hs_hi, hs_lo);

    gemm_tc_kernel<<<ggridK, 256, GEMM_SMEM>>>(hs_hi, hs_lo, NH, HIDD,
                                               bsw + OW1, TOPO, h1, NH, NN, HIDD, -1,
                                               nullptr, nullptr, nullptr, nullptr,
                                               nullptr, nullptr, nullptr, nullptr);
    gcn_gather_kernel<<<ngridK, 256>>>(h1, csr, off, dinv, gb1, hs_hi, hs_lo);

    gemm_tc_kernel<<<ggridK, 256, GEMM_SMEM>>>(hs_hi, hs_lo, NH, HIDD,
                                               bsw + OW2, TOPO, h1, NH, NN, HIDD, -1,
                                               nullptr, nullptr, nullptr, nullptr,
                                               nullptr, nullptr, nullptr, nullptr);
    gcn_gather_kernel<<<ngridK, 256>>>(h1, csr, off, dinv, gb2, hs_hi, hs_lo);

    gemm_tc_kernel<<<ggridK, 256, GEMM_SMEM>>>(hs_hi, hs_lo, NH, HIDD,
                                               bsw + OAW, TOPO, h1, NH, NN, HIDD, -1,
                                               nullptr, nullptr, nullptr, nullptr,
                                               aas, aad, as_, ad_);
    gat_gather_ln_kernel<<<agridK, 256>>>(h1, csr, off, as_, ad_, ab, lg, lb, outs);

    // fusion tail
    fuse_logits_kernel<<<cdiv(NN * 32, 256), 256>>>(hf, fb1, fW2, fb2, wbuf);
    combine_kernel<<<NN, 256>>>(wbuf, (float*)d_out);
}